// round 12
// baseline (speedup 1.0000x reference)
#include <cuda_runtime.h>
#include <cuda_bf16.h>
#include <math.h>
#include <stdint.h>

#define HW    1024
#define NPTS  65536
#define KC    1024
#define NELEM 4194304
#define ROWB  400          // tile row bytes: 192 bf16 (384B) + 16B pad

__device__ unsigned char g_ebt[8][128 * ROWB];  // bf16 [eh|el|eh] tiles per 128-code chunk
__device__ float  g_et[64 * KC];                // transposed emb [d][c] for cleanup
__device__ float  g_se[KC];
__device__ int    g_idx[NPTS];
__device__ int    g_hist[KC];
__device__ int    g_ncand;
__device__ int    g_cand[NPTS];
__device__ double g_sumsq;

// ---- vq smem byte offsets ----
#define OFF_A   0           // 128 x 400B = 51200
#define OFF_B0  51200       // 64 x 400B = 25600
#define OFF_B1  76800       // 25600 ; x staging [64][128] f32 spans B0..B0+32768
#define OFF_SE  102400      // 4096
#define OFF_SX  106496      // 512
#define OFF_FB1 107008
#define OFF_FI1 107520
#define OFF_FB2 108032
#define SMEM_TOTAL 108544   // x2 CTAs = 212KB <= 228KB/SM

__device__ __forceinline__ uint32_t smem_u32(const void* p) {
    uint32_t a;
    asm("{ .reg .u64 t; cvta.to.shared.u64 t, %1; cvt.u32.u64 %0, t; }" : "=r"(a) : "l"(p));
    return a;
}
__device__ __forceinline__ void cpa16(uint32_t dst, const void* src) {
    asm volatile("cp.async.cg.shared.global [%0], [%1], 16;" :: "r"(dst), "l"(src));
}
__device__ __forceinline__ void cpa_commit() { asm volatile("cp.async.commit_group;"); }
__device__ __forceinline__ void cpa_wait0()  { asm volatile("cp.async.wait_group 0;"); }
__device__ __forceinline__ void cpa_wait1()  { asm volatile("cp.async.wait_group 1;"); }

__device__ __forceinline__ void ldsm4(uint32_t& r0, uint32_t& r1, uint32_t& r2, uint32_t& r3,
                                      uint32_t addr) {
    asm volatile("ldmatrix.sync.aligned.m8n8.x4.shared.b16 {%0,%1,%2,%3}, [%4];"
                 : "=r"(r0), "=r"(r1), "=r"(r2), "=r"(r3) : "r"(addr));
}
__device__ __forceinline__ void mma16816(float* d, const uint32_t* a, uint32_t b0, uint32_t b1) {
    asm volatile("mma.sync.aligned.m16n8k16.row.col.f32.bf16.bf16.f32 "
                 "{%0,%1,%2,%3}, {%4,%5,%6,%7}, {%8,%9}, {%0,%1,%2,%3};"
                 : "+f"(d[0]), "+f"(d[1]), "+f"(d[2]), "+f"(d[3])
                 : "r"(a[0]), "r"(a[1]), "r"(a[2]), "r"(a[3]), "r"(b0), "r"(b1));
}

// ---- prep (8 blocks, one per 128-code chunk): bf16 tile + g_et + se + zeroing ----
// dyn smem: stg[128][65] f32 (33280B) | tile 51200B
__global__ void __launch_bounds__(256) prep_kernel(const float* __restrict__ emb) {
    extern __shared__ float psm[];
    float* stg = psm;                       // pitch 65
    char*  tile = (char*)psm + 33280;
    const int tid = threadIdx.x;
    const int chunk = blockIdx.x;
    const int c0 = chunk * 128;

#pragma unroll
    for (int q = 0; q < 8; ++q) {
        int fidx = q * 256 + tid;           // float4 id 0..2047
        int code = fidx >> 4, f4 = fidx & 15;
        float4 v = ((const float4*)(emb + (size_t)c0 * 64))[fidx];
        float* d = stg + code * 65 + f4 * 4;
        d[0] = v.x; d[1] = v.y; d[2] = v.z; d[3] = v.w;
    }

    if (tid < 128) {
        int code = c0 + tid;
        g_hist[code] = 0;
        const float4* r4 = (const float4*)(emb + (size_t)code * 64);
        float s = 0.f;
#pragma unroll
        for (int i = 0; i < 16; ++i) {
            float4 v = r4[i];
            s += v.x * v.x + v.y * v.y + v.z * v.z + v.w * v.w;
        }
        g_se[code] = s;
    }
    if (chunk == 0 && tid == 128) { g_sumsq = 0.0; g_ncand = 0; }
    __syncthreads();

    {
        int code = tid >> 1, hf = tid & 1;
        __nv_bfloat16* row = (__nv_bfloat16*)(tile + code * ROWB);
        const float* sr = stg + code * 65;
#pragma unroll
        for (int k = 0; k < 32; ++k) {
            int d = hf * 32 + k;
            float ev = sr[d];
            __nv_bfloat16 eh = __float2bfloat16(ev);
            __nv_bfloat16 el = __float2bfloat16(ev - __bfloat162float(eh));
            row[d]       = eh;
            row[64 + d]  = el;
            row[128 + d] = eh;
        }
    }
#pragma unroll
    for (int i = 0; i < 32; ++i) {
        int idx = i * 256 + tid;            // 0..8191
        int d = idx >> 7, cc = idx & 127;
        g_et[d * KC + c0 + cc] = stg[cc * 65 + d];
    }
    __syncthreads();
#pragma unroll
    for (int q = 0; q < 13; ++q) {
        int idx = q * 256 + tid;
        if (idx < 3200)
            ((float4*)g_ebt[chunk])[idx] = ((const float4*)tile)[idx];
    }
}

// ---- mma.sync vq: 128 pts x 1024 codes per block, 64-code chunks, 2 CTAs/SM,
//      software-pipelined fragments ----
__global__ void __launch_bounds__(256, 2) vq_kernel(const float* __restrict__ x) {
    extern __shared__ float sm[];
    const uint32_t smb = smem_u32(sm);
    char* smc = (char*)sm;
    const int tid = threadIdx.x;
    const int w = tid >> 5, lane = tid & 31;
    const int mg = w & 3;            // rows mg*32..mg*32+31
    const int cg = w >> 2;           // codes cg*32..cg*32+31 within 64-code chunk
    const int quad = lane >> 2, lane4 = lane & 3;
    const int bb = blockIdx.x >> 3, hw0 = (blockIdx.x & 7) << 7;
    const float* xb = x + ((size_t)bb << 16) + hw0;

    // G0: x staging at OFF_B0 (spans B0+part of B1), se
#pragma unroll
    for (int q = 0; q < 8; ++q) {
        int l = (q * 256 + tid) * 4;        // float idx in [64 d][128 p]
        cpa16(smb + OFF_B0 + l * 4, xb + (l >> 7) * HW + (l & 127));
    }
    cpa16(smb + OFF_SE + tid * 16, g_se + tid * 4);
    cpa_commit();
    cpa_wait0();
    __syncthreads();

    float* stage = (float*)(smc + OFF_B0);
    float* sxs   = (float*)(smc + OFF_SX);
    if (tid < 128) {
        float s = 0.f;
#pragma unroll
        for (int d = 0; d < 64; ++d) { float v = stage[d * 128 + tid]; s = fmaf(v, v, s); }
        sxs[tid] = s;
    }
    // build A tile: row p, cols [xh|xh|xl]
    {
        int p = tid >> 1, hf = tid & 1;
        __nv_bfloat16* ar = (__nv_bfloat16*)(smc + OFF_A + p * ROWB);
#pragma unroll
        for (int k = 0; k < 32; ++k) {
            int d = hf * 32 + k;
            float xv = stage[d * 128 + p];
            __nv_bfloat16 xh = __float2bfloat16(xv);
            __nv_bfloat16 xl = __float2bfloat16(xv - __bfloat162float(xh));
            ar[d]       = xh;
            ar[64 + d]  = xh;
            ar[128 + d] = xl;
        }
    }
    __syncthreads();            // staging dead; A + sxs ready

    // chunk0 -> B0, chunk1 -> B1 (each its own group)
#pragma unroll
    for (int q = 0; q < 7; ++q) {
        int idx = q * 256 + tid;
        if (idx < 1600) cpa16(smb + OFF_B0 + idx * 16, g_ebt[0] + idx * 16);
    }
    cpa_commit();
#pragma unroll
    for (int q = 0; q < 7; ++q) {
        int idx = q * 256 + tid;
        if (idx < 1600) cpa16(smb + OFF_B1 + idx * 16, (const char*)g_ebt[0] + 25600 + idx * 16);
    }
    cpa_commit();
    cpa_wait1();
    __syncthreads();

    const float* sef = (const float*)(smc + OFF_SE);
    float b1v[4], b2v[4];
    int   b1i[4];
#pragma unroll
    for (int s = 0; s < 4; ++s) { b1v[s] = 3.4e38f; b2v[s] = 3.4e38f; b1i[s] = 0; }

    const uint32_t Abase = smb + OFF_A + (uint32_t)(mg * 32 + (lane & 15)) * ROWB
                           + (uint32_t)((lane >> 4) * 16);
    const uint32_t brow = (lane & 7) + ((lane >> 4) << 3);
    const uint32_t Boff = (uint32_t)(cg * 32 + brow) * ROWB + (uint32_t)(((lane >> 3) & 1) * 16);

#define UPD(s, v, ci) \
    do { float _v = (v); \
         if (_v < b1v[s]) { b2v[s] = b1v[s]; b1v[s] = _v; b1i[s] = (ci); } \
         else if (_v < b2v[s]) b2v[s] = _v; } while (0)

    for (int c = 0; c < 16; ++c) {           // 16 chunks of 64 codes
        const uint32_t Bbase = smb + ((c & 1) ? OFF_B1 : OFF_B0) + Boff;
        float acc[2][4][4];
#pragma unroll
        for (int mt = 0; mt < 2; ++mt)
#pragma unroll
            for (int nt = 0; nt < 4; ++nt)
#pragma unroll
                for (int j = 0; j < 4; ++j) acc[mt][nt][j] = 0.f;

        // software-pipelined mainloop: prefetch ks+1 fragments during ks's mma
        uint32_t af[2][8], bf[2][8];
        ldsm4(af[0][0], af[0][1], af[0][2], af[0][3], Abase);
        ldsm4(af[0][4], af[0][5], af[0][6], af[0][7], Abase + 16 * ROWB);
        ldsm4(bf[0][0], bf[0][1], bf[0][2], bf[0][3], Bbase);
        ldsm4(bf[0][4], bf[0][5], bf[0][6], bf[0][7], Bbase + 16 * ROWB);
#pragma unroll
        for (int ks = 0; ks < 12; ++ks) {
            const int cur = ks & 1, nxt = cur ^ 1;
            if (ks < 11) {
                uint32_t ao = (uint32_t)(ks + 1) * 32;
                ldsm4(af[nxt][0], af[nxt][1], af[nxt][2], af[nxt][3], Abase + ao);
                ldsm4(af[nxt][4], af[nxt][5], af[nxt][6], af[nxt][7],
                      Abase + ao + 16 * ROWB);
                ldsm4(bf[nxt][0], bf[nxt][1], bf[nxt][2], bf[nxt][3], Bbase + ao);
                ldsm4(bf[nxt][4], bf[nxt][5], bf[nxt][6], bf[nxt][7],
                      Bbase + ao + 16 * ROWB);
            }
            mma16816(acc[0][0], &af[cur][0], bf[cur][0], bf[cur][1]);
            mma16816(acc[0][1], &af[cur][0], bf[cur][2], bf[cur][3]);
            mma16816(acc[1][0], &af[cur][4], bf[cur][0], bf[cur][1]);
            mma16816(acc[1][1], &af[cur][4], bf[cur][2], bf[cur][3]);
            mma16816(acc[0][2], &af[cur][0], bf[cur][4], bf[cur][5]);
            mma16816(acc[0][3], &af[cur][0], bf[cur][6], bf[cur][7]);
            mma16816(acc[1][2], &af[cur][4], bf[cur][4], bf[cur][5]);
            mma16816(acc[1][3], &af[cur][4], bf[cur][6], bf[cur][7]);
        }

        __syncthreads();        // all warps done reading buffer c
        // issue loads for chunk c+2 into the buffer just freed, then epilogue overlaps DMA
        if (c + 2 < 16) {
            uint32_t dst = (c & 1) ? OFF_B1 : OFF_B0;
            const char* src = (const char*)g_ebt[(c + 2) >> 1] + ((c + 2) & 1) * 25600;
#pragma unroll
            for (int q = 0; q < 7; ++q) {
                int idx = q * 256 + tid;
                if (idx < 1600) cpa16(smb + dst + idx * 16, src + idx * 16);
            }
        }
        cpa_commit();

        // epilogue: v = se - 2*dot, best-2 per row-slot (ascending code order)
        const int cb0 = c * 64 + cg * 32;
#pragma unroll
        for (int mt = 0; mt < 2; ++mt) {
#pragma unroll
            for (int nt = 0; nt < 4; ++nt) {
                int cbn = cb0 + nt * 8 + 2 * lane4;
                float se0 = sef[cbn], se1 = sef[cbn + 1];
                UPD(mt * 2 + 0, fmaf(-2.f, acc[mt][nt][0], se0), cbn);
                UPD(mt * 2 + 0, fmaf(-2.f, acc[mt][nt][1], se1), cbn + 1);
                UPD(mt * 2 + 1, fmaf(-2.f, acc[mt][nt][2], se0), cbn);
                UPD(mt * 2 + 1, fmaf(-2.f, acc[mt][nt][3], se1), cbn + 1);
            }
        }

        if (c < 15) { cpa_wait1(); __syncthreads(); }
    }
#undef UPD

    // reduce across 4 column-lanes per row (tie -> lower index)
#pragma unroll
    for (int off = 1; off < 4; off <<= 1) {
#pragma unroll
        for (int s = 0; s < 4; ++s) {
            float ov1 = __shfl_xor_sync(0xffffffffu, b1v[s], off);
            float ov2 = __shfl_xor_sync(0xffffffffu, b2v[s], off);
            int   oi  = __shfl_xor_sync(0xffffffffu, b1i[s], off);
            if (ov1 < b1v[s] || (ov1 == b1v[s] && oi < b1i[s])) {
                b2v[s] = fminf(b1v[s], ov2);
                b1v[s] = ov1; b1i[s] = oi;
            } else {
                b2v[s] = fminf(b2v[s], ov1);
            }
        }
    }

    float* fb1 = (float*)(smc + OFF_FB1);
    int*   fi1 = (int*)(smc + OFF_FI1);
    float* fb2 = (float*)(smc + OFF_FB2);
    if (cg == 0 && lane4 == 0) {
#pragma unroll
        for (int s = 0; s < 4; ++s) {
            int row = mg * 32 + (s >> 1) * 16 + (s & 1) * 8 + quad;
            fb1[row] = b1v[s]; fi1[row] = b1i[s]; fb2[row] = b2v[s];
        }
    }
    __syncthreads();
    if (cg == 1 && lane4 == 0) {
#pragma unroll
        for (int s = 0; s < 4; ++s) {
            int row = mg * 32 + (s >> 1) * 16 + (s & 1) * 8 + quad;
            float ov1 = fb1[row], ov2 = fb2[row];
            int   oi  = fi1[row];
            float nb1, nb2; int ni1;
            if (ov1 < b1v[s] || (ov1 == b1v[s] && oi < b1i[s])) {
                nb1 = ov1; ni1 = oi; nb2 = fminf(b1v[s], ov2);
            } else {
                nb1 = b1v[s]; ni1 = b1i[s]; nb2 = fminf(ov1, b2v[s]);
            }
            int pt = (bb << 10) + hw0 + row;
            g_idx[pt] = ni1;
            float tau = 6e-5f * (sxs[row] + 64.f) + 1e-3f;
            if (nb2 - nb1 < tau) {
                int t = atomicAdd(&g_ncand, 1);
                g_cand[t] = pt;
            }
        }
    }
}

// ---- exact re-solve for flagged points: coalesced g_et reads, exact scalar order ----
__global__ void __launch_bounds__(256) cleanup_kernel(const float* __restrict__ x) {
    __shared__ float xs[64];
    __shared__ float rv[256];
    __shared__ int   ri[256];
    const int tid = threadIdx.x;
    const int n = g_ncand;
    for (int ci = blockIdx.x; ci < n; ci += gridDim.x) {
        int pt = g_cand[ci];
        int b = pt >> 10, hw = pt & 1023;
        if (tid < 64) xs[tid] = x[((size_t)b << 16) + tid * HW + hw];
        __syncthreads();
        float sx = 0.f;
#pragma unroll
        for (int d = 0; d < 64; ++d) sx = fmaf(xs[d], xs[d], sx);
        float dot0 = 0.f, dot1 = 0.f, dot2 = 0.f, dot3 = 0.f;
#pragma unroll
        for (int d = 0; d < 64; ++d) {
            const float* er = g_et + d * KC + tid;
            float xv = xs[d];
            dot0 = fmaf(xv, er[0],   dot0);
            dot1 = fmaf(xv, er[256], dot1);
            dot2 = fmaf(xv, er[512], dot2);
            dot3 = fmaf(xv, er[768], dot3);
        }
        float bv = 3.4e38f; int bi = 0;
        float v;
        v = __fadd_rn(__fmaf_rn(-2.f, dot0, sx), g_se[tid]);
        if (v < bv) { bv = v; bi = tid; }
        v = __fadd_rn(__fmaf_rn(-2.f, dot1, sx), g_se[tid + 256]);
        if (v < bv) { bv = v; bi = tid + 256; }
        v = __fadd_rn(__fmaf_rn(-2.f, dot2, sx), g_se[tid + 512]);
        if (v < bv) { bv = v; bi = tid + 512; }
        v = __fadd_rn(__fmaf_rn(-2.f, dot3, sx), g_se[tid + 768]);
        if (v < bv) { bv = v; bi = tid + 768; }
        rv[tid] = bv; ri[tid] = bi;
        __syncthreads();
        for (int s = 128; s; s >>= 1) {
            if (tid < s) {
                if (rv[tid + s] < rv[tid] ||
                    (rv[tid + s] == rv[tid] && ri[tid + s] < ri[tid])) {
                    rv[tid] = rv[tid + s]; ri[tid] = ri[tid + s];
                }
            }
            __syncthreads();
        }
        if (tid == 0) g_idx[pt] = ri[0];
        __syncthreads();
    }
}

// ---- gather to NCHW + hist + loss partial ----
__global__ void __launch_bounds__(256) gather_kernel(const float* __restrict__ x,
                                                     const float* __restrict__ emb,
                                                     float* __restrict__ out) {
    __shared__ int   sidx[64];
    __shared__ float qs[64 * 65];
    __shared__ float red[8];
    const int tid = threadIdx.x;
    const int bb  = blockIdx.x >> 4;
    const int hw0 = (blockIdx.x & 15) << 6;

    if (tid < 64) {
        int k = g_idx[(bb << 10) + hw0 + tid];
        sidx[tid] = k;
        atomicAdd(&g_hist[k], 1);
    }
    __syncthreads();
    {
        int p = tid >> 2, i = tid & 3;
        const float4* er = (const float4*)(emb + (size_t)sidx[p] * 64) + i * 4;
#pragma unroll
        for (int k = 0; k < 4; ++k) {
            float4 v = er[k];
            int d = i * 16 + k * 4;
            qs[p * 65 + d]     = v.x;
            qs[p * 65 + d + 1] = v.y;
            qs[p * 65 + d + 2] = v.z;
            qs[p * 65 + d + 3] = v.w;
        }
    }
    __syncthreads();
    const int lane = tid & 31, w = tid >> 5;
    float s = 0.f;
#pragma unroll
    for (int c8 = 0; c8 < 8; ++c8) {
        int c = w * 8 + c8;
        size_t ob = (((size_t)bb << 6) + c) * HW + hw0;
#pragma unroll
        for (int ph = 0; ph < 2; ++ph) {
            int p = ph * 32 + lane;
            float q  = qs[p * 65 + c];
            float xv = x[ob + p];
            out[ob + p] = q;
            float d = q - xv;
            s = fmaf(d, d, s);
        }
    }
#pragma unroll
    for (int off = 16; off; off >>= 1) s += __shfl_xor_sync(0xffffffffu, s, off);
    if (lane == 0) red[w] = s;
    __syncthreads();
    if (tid == 0) {
        float t = 0.f;
#pragma unroll
        for (int i = 0; i < 8; ++i) t += red[i];
        atomicAdd(&g_sumsq, (double)t);
    }
}

// ---- loss + perplexity ----
__global__ void __launch_bounds__(1024) final_kernel(float* __restrict__ out, int nq) {
    __shared__ float red[32];
    int t = threadIdx.x;
    float p = (float)g_hist[t] * (1.0f / 65536.0f);
    float term = p * logf(p + 1e-10f);
#pragma unroll
    for (int off = 16; off; off >>= 1) term += __shfl_xor_sync(0xffffffffu, term, off);
    if ((t & 31) == 0) red[t >> 5] = term;
    __syncthreads();
    if (t < 32) {
        float v = red[t];
#pragma unroll
        for (int off = 16; off; off >>= 1) v += __shfl_xor_sync(0xffffffffu, v, off);
        if (t == 0) {
            float m = (float)(g_sumsq * (1.0 / (double)NELEM));
            out[nq]     = 1.25f * m;
            out[nq + 1] = expf(-v);
        }
    }
}

extern "C" void kernel_launch(void* const* d_in, const int* in_sizes, int n_in,
                              void* d_out, int out_size) {
    const float* x   = (const float*)d_in[0];
    const float* emb = (const float*)d_in[1];
    if (n_in >= 2 && in_sizes[0] == KC * 64 && in_sizes[1] == NELEM) {
        const float* tmp = x; x = emb; emb = tmp;
    }
    float* out = (float*)d_out;
    int nq = out_size - 2;

    cudaFuncSetAttribute(vq_kernel, cudaFuncAttributeMaxDynamicSharedMemorySize, SMEM_TOTAL);
    cudaFuncSetAttribute(prep_kernel, cudaFuncAttributeMaxDynamicSharedMemorySize, 84480);

    prep_kernel<<<8, 256, 84480>>>(emb);
    vq_kernel<<<512, 256, SMEM_TOTAL>>>(x);
    cleanup_kernel<<<1024, 256>>>(x);
    gather_kernel<<<NPTS / 64, 256>>>(x, emb, out);
    final_kernel<<<1, 1024>>>(out, nq);
}

// round 13
// speedup vs baseline: 1.0370x; 1.0370x over previous
#include <cuda_runtime.h>
#include <cuda_bf16.h>
#include <math.h>
#include <stdint.h>

#define HW    1024
#define NPTS  65536
#define KC    1024
#define NELEM 4194304
#define ROWB  400          // tile row bytes: 192 bf16 (384B) + 16B pad

__device__ unsigned char g_ebt[8][128 * ROWB];  // bf16 [eh|el|eh] tiles per 128-code chunk
__device__ float  g_et[64 * KC];                // transposed emb [d][c] for exact re-solve
__device__ float  g_se[KC];
__device__ int    g_idx[NPTS];
__device__ int    g_hist[KC];
__device__ int    g_done;
__device__ double g_sumsq;

// ---- vq smem byte offsets ----
#define OFF_A   0           // 128 x 400B = 51200
#define OFF_B0  51200       // 64 x 400B = 25600
#define OFF_B1  76800       // 25600 ; x staging [64][128] f32 spans B0..B0+32768
#define OFF_SE  102400      // 4096
#define OFF_SX  106496      // 512
#define OFF_FB1 107008
#define OFF_FI1 107520
#define OFF_FB2 108032
#define OFF_CND 108544      // 128 ints candidate rows
#define OFF_CNT 109056      // counter
#define SMEM_TOTAL 109088   // x2 CTAs = 218KB <= 228KB/SM

__device__ __forceinline__ uint32_t smem_u32(const void* p) {
    uint32_t a;
    asm("{ .reg .u64 t; cvta.to.shared.u64 t, %1; cvt.u32.u64 %0, t; }" : "=r"(a) : "l"(p));
    return a;
}
__device__ __forceinline__ void cpa16(uint32_t dst, const void* src) {
    asm volatile("cp.async.cg.shared.global [%0], [%1], 16;" :: "r"(dst), "l"(src));
}
__device__ __forceinline__ void cpa_commit() { asm volatile("cp.async.commit_group;"); }
__device__ __forceinline__ void cpa_wait0()  { asm volatile("cp.async.wait_group 0;"); }
__device__ __forceinline__ void cpa_wait1()  { asm volatile("cp.async.wait_group 1;"); }

__device__ __forceinline__ void ldsm4(uint32_t& r0, uint32_t& r1, uint32_t& r2, uint32_t& r3,
                                      uint32_t addr) {
    asm volatile("ldmatrix.sync.aligned.m8n8.x4.shared.b16 {%0,%1,%2,%3}, [%4];"
                 : "=r"(r0), "=r"(r1), "=r"(r2), "=r"(r3) : "r"(addr));
}
__device__ __forceinline__ void mma16816(float* d, uint32_t a0, uint32_t a1, uint32_t a2,
                                         uint32_t a3, uint32_t b0, uint32_t b1) {
    asm volatile("mma.sync.aligned.m16n8k16.row.col.f32.bf16.bf16.f32 "
                 "{%0,%1,%2,%3}, {%4,%5,%6,%7}, {%8,%9}, {%0,%1,%2,%3};"
                 : "+f"(d[0]), "+f"(d[1]), "+f"(d[2]), "+f"(d[3])
                 : "r"(a0), "r"(a1), "r"(a2), "r"(a3), "r"(b0), "r"(b1));
}

// ---- prep (8 blocks, one per 128-code chunk): bf16 tile + g_et + se + zeroing ----
// dyn smem: stg[128][65] f32 (33280B) | tile 51200B
__global__ void __launch_bounds__(256) prep_kernel(const float* __restrict__ emb) {
    extern __shared__ float psm[];
    float* stg = psm;                       // pitch 65
    char*  tile = (char*)psm + 33280;
    const int tid = threadIdx.x;
    const int chunk = blockIdx.x;
    const int c0 = chunk * 128;

#pragma unroll
    for (int q = 0; q < 8; ++q) {
        int fidx = q * 256 + tid;           // float4 id 0..2047
        int code = fidx >> 4, f4 = fidx & 15;
        float4 v = ((const float4*)(emb + (size_t)c0 * 64))[fidx];
        float* d = stg + code * 65 + f4 * 4;
        d[0] = v.x; d[1] = v.y; d[2] = v.z; d[3] = v.w;
    }

    if (tid < 128) {
        int code = c0 + tid;
        g_hist[code] = 0;
        const float4* r4 = (const float4*)(emb + (size_t)code * 64);
        float s = 0.f;
#pragma unroll
        for (int i = 0; i < 16; ++i) {
            float4 v = r4[i];
            s += v.x * v.x + v.y * v.y + v.z * v.z + v.w * v.w;
        }
        g_se[code] = s;
    }
    if (chunk == 0 && tid == 128) { g_sumsq = 0.0; g_done = 0; }
    __syncthreads();

    {
        int code = tid >> 1, hf = tid & 1;
        __nv_bfloat16* row = (__nv_bfloat16*)(tile + code * ROWB);
        const float* sr = stg + code * 65;
#pragma unroll
        for (int k = 0; k < 32; ++k) {
            int d = hf * 32 + k;
            float ev = sr[d];
            __nv_bfloat16 eh = __float2bfloat16(ev);
            __nv_bfloat16 el = __float2bfloat16(ev - __bfloat162float(eh));
            row[d]       = eh;
            row[64 + d]  = el;
            row[128 + d] = eh;
        }
    }
#pragma unroll
    for (int i = 0; i < 32; ++i) {
        int idx = i * 256 + tid;            // 0..8191
        int d = idx >> 7, cc = idx & 127;
        g_et[d * KC + c0 + cc] = stg[cc * 65 + d];
    }
    __syncthreads();
#pragma unroll
    for (int q = 0; q < 13; ++q) {
        int idx = q * 256 + tid;
        if (idx < 3200)
            ((float4*)g_ebt[chunk])[idx] = ((const float4*)tile)[idx];
    }
}

// ---- mma.sync vq: 128 pts x 1024 codes per block, 64-code chunks, 2 CTAs/SM,
//      + in-block exact re-solve for margin-flagged points ----
__global__ void __launch_bounds__(256, 2) vq_kernel(const float* __restrict__ x) {
    extern __shared__ float sm[];
    const uint32_t smb = smem_u32(sm);
    char* smc = (char*)sm;
    const int tid = threadIdx.x;
    const int w = tid >> 5, lane = tid & 31;
    const int mg = w & 3;            // rows mg*32..mg*32+31
    const int cg = w >> 2;           // codes cg*32..cg*32+31 within 64-code chunk
    const int quad = lane >> 2, lane4 = lane & 3;
    const int bb = blockIdx.x >> 3, hw0 = (blockIdx.x & 7) << 7;
    const float* xb = x + ((size_t)bb << 16) + hw0;

    int* scnt = (int*)(smc + OFF_CNT);
    int* scand = (int*)(smc + OFF_CND);
    if (tid == 0) *scnt = 0;

    // G0: x staging at OFF_B0 (spans B0+part of B1), se
#pragma unroll
    for (int q = 0; q < 8; ++q) {
        int l = (q * 256 + tid) * 4;        // float idx in [64 d][128 p]
        cpa16(smb + OFF_B0 + l * 4, xb + (l >> 7) * HW + (l & 127));
    }
    cpa16(smb + OFF_SE + tid * 16, g_se + tid * 4);
    cpa_commit();
    cpa_wait0();
    __syncthreads();

    float* stage = (float*)(smc + OFF_B0);
    float* sxs   = (float*)(smc + OFF_SX);
    if (tid < 128) {
        float s = 0.f;
#pragma unroll
        for (int d = 0; d < 64; ++d) { float v = stage[d * 128 + tid]; s = fmaf(v, v, s); }
        sxs[tid] = s;
    }
    // build A tile: row p, cols [xh|xh|xl]
    {
        int p = tid >> 1, hf = tid & 1;
        __nv_bfloat16* ar = (__nv_bfloat16*)(smc + OFF_A + p * ROWB);
#pragma unroll
        for (int k = 0; k < 32; ++k) {
            int d = hf * 32 + k;
            float xv = stage[d * 128 + p];
            __nv_bfloat16 xh = __float2bfloat16(xv);
            __nv_bfloat16 xl = __float2bfloat16(xv - __bfloat162float(xh));
            ar[d]       = xh;
            ar[64 + d]  = xh;
            ar[128 + d] = xl;
        }
    }
    __syncthreads();            // staging dead; A + sxs ready

    // chunk0 -> B0, chunk1 -> B1 (each its own group)
#pragma unroll
    for (int q = 0; q < 7; ++q) {
        int idx = q * 256 + tid;
        if (idx < 1600) cpa16(smb + OFF_B0 + idx * 16, g_ebt[0] + idx * 16);
    }
    cpa_commit();
#pragma unroll
    for (int q = 0; q < 7; ++q) {
        int idx = q * 256 + tid;
        if (idx < 1600) cpa16(smb + OFF_B1 + idx * 16, (const char*)g_ebt[0] + 25600 + idx * 16);
    }
    cpa_commit();
    cpa_wait1();
    __syncthreads();

    const float* sef = (const float*)(smc + OFF_SE);
    float b1v[4], b2v[4];
    int   b1i[4];
#pragma unroll
    for (int s = 0; s < 4; ++s) { b1v[s] = 3.4e38f; b2v[s] = 3.4e38f; b1i[s] = 0; }

    const uint32_t Abase = smb + OFF_A + (uint32_t)(mg * 32 + (lane & 15)) * ROWB
                           + (uint32_t)((lane >> 4) * 16);
    const uint32_t brow = (lane & 7) + ((lane >> 4) << 3);
    const uint32_t Boff = (uint32_t)(cg * 32 + brow) * ROWB + (uint32_t)(((lane >> 3) & 1) * 16);

#define UPD(s, v, ci) \
    do { float _v = (v); \
         if (_v < b1v[s]) { b2v[s] = b1v[s]; b1v[s] = _v; b1i[s] = (ci); } \
         else if (_v < b2v[s]) b2v[s] = _v; } while (0)

    for (int c = 0; c < 16; ++c) {           // 16 chunks of 64 codes
        const uint32_t Bbase = smb + ((c & 1) ? OFF_B1 : OFF_B0) + Boff;
        float acc[2][4][4];
#pragma unroll
        for (int mt = 0; mt < 2; ++mt)
#pragma unroll
            for (int nt = 0; nt < 4; ++nt)
#pragma unroll
                for (int j = 0; j < 4; ++j) acc[mt][nt][j] = 0.f;

#pragma unroll
        for (int ks = 0; ks < 12; ++ks) {
            uint32_t a00, a01, a02, a03, a10, a11, a12, a13;
            ldsm4(a00, a01, a02, a03, Abase + ks * 32);
            ldsm4(a10, a11, a12, a13, Abase + ks * 32 + 16 * ROWB);
#pragma unroll
            for (int np = 0; np < 2; ++np) {
                uint32_t b0, b1, b2, b3;
                ldsm4(b0, b1, b2, b3, Bbase + ks * 32 + (uint32_t)np * (16 * ROWB));
                mma16816(acc[0][2 * np],     a00, a01, a02, a03, b0, b1);
                mma16816(acc[0][2 * np + 1], a00, a01, a02, a03, b2, b3);
                mma16816(acc[1][2 * np],     a10, a11, a12, a13, b0, b1);
                mma16816(acc[1][2 * np + 1], a10, a11, a12, a13, b2, b3);
            }
        }

        const int cb0 = c * 64 + cg * 32;
#pragma unroll
        for (int mt = 0; mt < 2; ++mt) {
#pragma unroll
            for (int nt = 0; nt < 4; ++nt) {
                int cbn = cb0 + nt * 8 + 2 * lane4;
                float se0 = sef[cbn], se1 = sef[cbn + 1];
                UPD(mt * 2 + 0, fmaf(-2.f, acc[mt][nt][0], se0), cbn);
                UPD(mt * 2 + 0, fmaf(-2.f, acc[mt][nt][1], se1), cbn + 1);
                UPD(mt * 2 + 1, fmaf(-2.f, acc[mt][nt][2], se0), cbn);
                UPD(mt * 2 + 1, fmaf(-2.f, acc[mt][nt][3], se1), cbn + 1);
            }
        }

        __syncthreads();
        if (c + 2 < 16) {
            uint32_t dst = (c & 1) ? OFF_B1 : OFF_B0;
            const char* src = (const char*)g_ebt[(c + 2) >> 1] + ((c + 2) & 1) * 25600;
#pragma unroll
            for (int q = 0; q < 7; ++q) {
                int idx = q * 256 + tid;
                if (idx < 1600) cpa16(smb + dst + idx * 16, src + idx * 16);
            }
        }
        cpa_commit();
        if (c < 15) { cpa_wait1(); __syncthreads(); }
    }
#undef UPD

    // reduce across 4 column-lanes per row (tie -> lower index)
#pragma unroll
    for (int off = 1; off < 4; off <<= 1) {
#pragma unroll
        for (int s = 0; s < 4; ++s) {
            float ov1 = __shfl_xor_sync(0xffffffffu, b1v[s], off);
            float ov2 = __shfl_xor_sync(0xffffffffu, b2v[s], off);
            int   oi  = __shfl_xor_sync(0xffffffffu, b1i[s], off);
            if (ov1 < b1v[s] || (ov1 == b1v[s] && oi < b1i[s])) {
                b2v[s] = fminf(b1v[s], ov2);
                b1v[s] = ov1; b1i[s] = oi;
            } else {
                b2v[s] = fminf(b2v[s], ov1);
            }
        }
    }

    float* fb1 = (float*)(smc + OFF_FB1);
    int*   fi1 = (int*)(smc + OFF_FI1);
    float* fb2 = (float*)(smc + OFF_FB2);
    if (cg == 0 && lane4 == 0) {
#pragma unroll
        for (int s = 0; s < 4; ++s) {
            int row = mg * 32 + (s >> 1) * 16 + (s & 1) * 8 + quad;
            fb1[row] = b1v[s]; fi1[row] = b1i[s]; fb2[row] = b2v[s];
        }
    }
    __syncthreads();
    if (cg == 1 && lane4 == 0) {
#pragma unroll
        for (int s = 0; s < 4; ++s) {
            int row = mg * 32 + (s >> 1) * 16 + (s & 1) * 8 + quad;
            float ov1 = fb1[row], ov2 = fb2[row];
            int   oi  = fi1[row];
            float nb1, nb2; int ni1;
            if (ov1 < b1v[s] || (ov1 == b1v[s] && oi < b1i[s])) {
                nb1 = ov1; ni1 = oi; nb2 = fminf(b1v[s], ov2);
            } else {
                nb1 = b1v[s]; ni1 = b1i[s]; nb2 = fminf(ov1, b2v[s]);
            }
            int pt = (bb << 10) + hw0 + row;
            g_idx[pt] = ni1;
            float tau = 6e-5f * (sxs[row] + 64.f) + 1e-3f;
            if (nb2 - nb1 < tau) {
                int t = atomicAdd(scnt, 1);
                scand[t] = row;
            }
        }
    }
    __syncthreads();

    // ---- in-block exact re-solve of flagged points (bit-exact cleanup path) ----
    const int nc = *scnt;
    float* xs = (float*)(smc + OFF_B0);          // B buffers dead now
    float* rv = xs + 64;
    int*   ri = (int*)(rv + 256);
    for (int ci = 0; ci < nc; ++ci) {
        int row = scand[ci];
        if (tid < 64) xs[tid] = x[((size_t)bb << 16) + tid * HW + hw0 + row];
        __syncthreads();
        float sx = sxs[row];                     // bitwise == serial-fmaf recompute
        float dot0 = 0.f, dot1 = 0.f, dot2 = 0.f, dot3 = 0.f;
#pragma unroll
        for (int d = 0; d < 64; ++d) {
            const float* er = g_et + d * KC + tid;
            float xv = xs[d];
            dot0 = fmaf(xv, er[0],   dot0);
            dot1 = fmaf(xv, er[256], dot1);
            dot2 = fmaf(xv, er[512], dot2);
            dot3 = fmaf(xv, er[768], dot3);
        }
        float bv = 3.4e38f; int bi = 0;
        float v;
        v = __fadd_rn(__fmaf_rn(-2.f, dot0, sx), sef[tid]);
        if (v < bv) { bv = v; bi = tid; }
        v = __fadd_rn(__fmaf_rn(-2.f, dot1, sx), sef[tid + 256]);
        if (v < bv) { bv = v; bi = tid + 256; }
        v = __fadd_rn(__fmaf_rn(-2.f, dot2, sx), sef[tid + 512]);
        if (v < bv) { bv = v; bi = tid + 512; }
        v = __fadd_rn(__fmaf_rn(-2.f, dot3, sx), sef[tid + 768]);
        if (v < bv) { bv = v; bi = tid + 768; }
        rv[tid] = bv; ri[tid] = bi;
        __syncthreads();
        for (int s = 128; s; s >>= 1) {
            if (tid < s) {
                if (rv[tid + s] < rv[tid] ||
                    (rv[tid + s] == rv[tid] && ri[tid + s] < ri[tid])) {
                    rv[tid] = rv[tid + s]; ri[tid] = ri[tid + s];
                }
            }
            __syncthreads();
        }
        if (tid == 0) g_idx[(bb << 10) + hw0 + row] = ri[0];
        __syncthreads();
    }
}

// ---- gather to NCHW + hist + loss partial + fused final (last block) ----
__global__ void __launch_bounds__(256) gather_kernel(const float* __restrict__ x,
                                                     const float* __restrict__ emb,
                                                     float* __restrict__ out, int nq) {
    __shared__ int   sidx[64];
    __shared__ float qs[64 * 65];
    __shared__ float red[8];
    __shared__ int   lastblk;
    const int tid = threadIdx.x;
    const int bb  = blockIdx.x >> 4;
    const int hw0 = (blockIdx.x & 15) << 6;

    if (tid < 64) {
        int k = g_idx[(bb << 10) + hw0 + tid];
        sidx[tid] = k;
        atomicAdd(&g_hist[k], 1);
    }
    __syncthreads();
    {
        int p = tid >> 2, i = tid & 3;
        const float4* er = (const float4*)(emb + (size_t)sidx[p] * 64) + i * 4;
#pragma unroll
        for (int k = 0; k < 4; ++k) {
            float4 v = er[k];
            int d = i * 16 + k * 4;
            qs[p * 65 + d]     = v.x;
            qs[p * 65 + d + 1] = v.y;
            qs[p * 65 + d + 2] = v.z;
            qs[p * 65 + d + 3] = v.w;
        }
    }
    __syncthreads();
    const int lane = tid & 31, w = tid >> 5;
    float s = 0.f;
#pragma unroll
    for (int c8 = 0; c8 < 8; ++c8) {
        int c = w * 8 + c8;
        size_t ob = (((size_t)bb << 6) + c) * HW + hw0;
#pragma unroll
        for (int ph = 0; ph < 2; ++ph) {
            int p = ph * 32 + lane;
            float q  = qs[p * 65 + c];
            float xv = x[ob + p];
            out[ob + p] = q;
            float d = q - xv;
            s = fmaf(d, d, s);
        }
    }
#pragma unroll
    for (int off = 16; off; off >>= 1) s += __shfl_xor_sync(0xffffffffu, s, off);
    if (lane == 0) red[w] = s;
    __syncthreads();
    if (tid == 0) {
        float t = 0.f;
#pragma unroll
        for (int i = 0; i < 8; ++i) t += red[i];
        atomicAdd(&g_sumsq, (double)t);
    }

    // completion counter: last block computes loss + perplexity
    __threadfence();
    __syncthreads();
    if (tid == 0) lastblk = (atomicAdd(&g_done, 1) == (int)gridDim.x - 1);
    __syncthreads();
    if (lastblk) {
        __threadfence();
        float term = 0.f;
#pragma unroll
        for (int k = 0; k < 4; ++k) {
            float p = (float)g_hist[tid + k * 256] * (1.0f / 65536.0f);
            term += p * logf(p + 1e-10f);
        }
#pragma unroll
        for (int off = 16; off; off >>= 1) term += __shfl_xor_sync(0xffffffffu, term, off);
        if (lane == 0) red[w] = term;
        __syncthreads();
        if (tid == 0) {
            float v = 0.f;
#pragma unroll
            for (int i = 0; i < 8; ++i) v += red[i];
            float m = (float)(g_sumsq * (1.0 / (double)NELEM));
            out[nq]     = 1.25f * m;
            out[nq + 1] = expf(-v);
        }
    }
}

extern "C" void kernel_launch(void* const* d_in, const int* in_sizes, int n_in,
                              void* d_out, int out_size) {
    const float* x   = (const float*)d_in[0];
    const float* emb = (const float*)d_in[1];
    if (n_in >= 2 && in_sizes[0] == KC * 64 && in_sizes[1] == NELEM) {
        const float* tmp = x; x = emb; emb = tmp;
    }
    float* out = (float*)d_out;
    int nq = out_size - 2;

    cudaFuncSetAttribute(vq_kernel, cudaFuncAttributeMaxDynamicSharedMemorySize, SMEM_TOTAL);
    cudaFuncSetAttribute(prep_kernel, cudaFuncAttributeMaxDynamicSharedMemorySize, 84480);

    prep_kernel<<<8, 256, 84480>>>(emb);
    vq_kernel<<<512, 256, SMEM_TOTAL>>>(x);
    gather_kernel<<<NPTS / 64, 256>>>(x, emb, out, nq);
}

// round 14
// speedup vs baseline: 1.1219x; 1.0819x over previous
#include <cuda_runtime.h>
#include <cuda_bf16.h>
#include <math.h>
#include <stdint.h>

#define HW    1024
#define NPTS  65536
#define KC    1024
#define NELEM 4194304
#define ROWB  400          // tile row bytes: 192 bf16 (384B) + 16B pad

__device__ unsigned char g_ebt[8][128 * ROWB];  // bf16 [eh|el|eh] tiles per 128-code chunk
__device__ float  g_et[64 * KC];                // transposed emb [d][c] for exact re-solve
__device__ float  g_se[KC];
__device__ int    g_idx[NPTS];
__device__ int    g_hist[KC];
__device__ int    g_done;
__device__ double g_sumsq;

// ---- vq smem byte offsets ----
#define OFF_A   0           // 128 x 400B = 51200
#define OFF_B0  51200       // 64 x 400B = 25600
#define OFF_B1  76800       // 25600 ; x staging [64][128] f32 spans B0..B0+32768
#define OFF_SE  102400      // 4096
#define OFF_SX  106496      // 512
#define OFF_FB1 107008
#define OFF_FI1 107520
#define OFF_FB2 108032
#define OFF_CND 108544      // 128 ints candidate rows
#define OFF_CNT 109056      // counter
#define SMEM_TOTAL 109088   // x2 CTAs = 218KB <= 228KB/SM

__device__ __forceinline__ uint32_t smem_u32(const void* p) {
    uint32_t a;
    asm("{ .reg .u64 t; cvta.to.shared.u64 t, %1; cvt.u32.u64 %0, t; }" : "=r"(a) : "l"(p));
    return a;
}
__device__ __forceinline__ void cpa16(uint32_t dst, const void* src) {
    asm volatile("cp.async.cg.shared.global [%0], [%1], 16;" :: "r"(dst), "l"(src));
}
__device__ __forceinline__ void cpa_commit() { asm volatile("cp.async.commit_group;"); }
__device__ __forceinline__ void cpa_wait0()  { asm volatile("cp.async.wait_group 0;"); }
__device__ __forceinline__ void cpa_wait1()  { asm volatile("cp.async.wait_group 1;"); }

__device__ __forceinline__ void ldsm4(uint32_t& r0, uint32_t& r1, uint32_t& r2, uint32_t& r3,
                                      uint32_t addr) {
    asm volatile("ldmatrix.sync.aligned.m8n8.x4.shared.b16 {%0,%1,%2,%3}, [%4];"
                 : "=r"(r0), "=r"(r1), "=r"(r2), "=r"(r3) : "r"(addr));
}
__device__ __forceinline__ void mma16816(float* d, const uint32_t* a, uint32_t b0, uint32_t b1) {
    asm volatile("mma.sync.aligned.m16n8k16.row.col.f32.bf16.bf16.f32 "
                 "{%0,%1,%2,%3}, {%4,%5,%6,%7}, {%8,%9}, {%0,%1,%2,%3};"
                 : "+f"(d[0]), "+f"(d[1]), "+f"(d[2]), "+f"(d[3])
                 : "r"(a[0]), "r"(a[1]), "r"(a[2]), "r"(a[3]), "r"(b0), "r"(b1));
}

// ---- prep (8 blocks, one per 128-code chunk): bf16 tile + g_et + se + zeroing ----
// dyn smem: stg[128][65] f32 (33280B) | tile 51200B
__global__ void __launch_bounds__(256) prep_kernel(const float* __restrict__ emb) {
    extern __shared__ float psm[];
    float* stg = psm;                       // pitch 65
    char*  tile = (char*)psm + 33280;
    const int tid = threadIdx.x;
    const int chunk = blockIdx.x;
    const int c0 = chunk * 128;

#pragma unroll
    for (int q = 0; q < 8; ++q) {
        int fidx = q * 256 + tid;           // float4 id 0..2047
        int code = fidx >> 4, f4 = fidx & 15;
        float4 v = ((const float4*)(emb + (size_t)c0 * 64))[fidx];
        float* d = stg + code * 65 + f4 * 4;
        d[0] = v.x; d[1] = v.y; d[2] = v.z; d[3] = v.w;
    }

    if (tid < 128) {
        int code = c0 + tid;
        g_hist[code] = 0;
        const float4* r4 = (const float4*)(emb + (size_t)code * 64);
        float s = 0.f;
#pragma unroll
        for (int i = 0; i < 16; ++i) {
            float4 v = r4[i];
            s += v.x * v.x + v.y * v.y + v.z * v.z + v.w * v.w;
        }
        g_se[code] = s;
    }
    if (chunk == 0 && tid == 128) { g_sumsq = 0.0; g_done = 0; }
    __syncthreads();

    {
        int code = tid >> 1, hf = tid & 1;
        __nv_bfloat16* row = (__nv_bfloat16*)(tile + code * ROWB);
        const float* sr = stg + code * 65;
#pragma unroll
        for (int k = 0; k < 32; ++k) {
            int d = hf * 32 + k;
            float ev = sr[d];
            __nv_bfloat16 eh = __float2bfloat16(ev);
            __nv_bfloat16 el = __float2bfloat16(ev - __bfloat162float(eh));
            row[d]       = eh;   // eh block (k 0..63)
            row[64 + d]  = el;   // el block (k 64..127)
        }
    }
#pragma unroll
    for (int i = 0; i < 32; ++i) {
        int idx = i * 256 + tid;            // 0..8191
        int d = idx >> 7, cc = idx & 127;
        g_et[d * KC + c0 + cc] = stg[cc * 65 + d];
    }
    __syncthreads();
#pragma unroll
    for (int q = 0; q < 13; ++q) {
        int idx = q * 256 + tid;
        if (idx < 3200)
            ((float4*)g_ebt[chunk])[idx] = ((const float4*)tile)[idx];
    }
}

// ---- mma.sync vq: 128 pts x 1024 codes per block, unique-k restructured mainloop,
//      xh fragments register-resident across all chunks; in-block exact re-solve ----
__global__ void __launch_bounds__(256, 2) vq_kernel(const float* __restrict__ x) {
    extern __shared__ float sm[];
    const uint32_t smb = smem_u32(sm);
    char* smc = (char*)sm;
    const int tid = threadIdx.x;
    const int w = tid >> 5, lane = tid & 31;
    const int mg = w & 3;            // rows mg*32..mg*32+31
    const int cg = w >> 2;           // codes cg*32..cg*32+31 within 64-code chunk
    const int quad = lane >> 2, lane4 = lane & 3;
    const int bb = blockIdx.x >> 3, hw0 = (blockIdx.x & 7) << 7;
    const float* xb = x + ((size_t)bb << 16) + hw0;

    int* scnt = (int*)(smc + OFF_CNT);
    int* scand = (int*)(smc + OFF_CND);
    if (tid == 0) *scnt = 0;

    // G0: x staging at OFF_B0 (spans B0+part of B1), se
#pragma unroll
    for (int q = 0; q < 8; ++q) {
        int l = (q * 256 + tid) * 4;        // float idx in [64 d][128 p]
        cpa16(smb + OFF_B0 + l * 4, xb + (l >> 7) * HW + (l & 127));
    }
    cpa16(smb + OFF_SE + tid * 16, g_se + tid * 4);
    cpa_commit();
    cpa_wait0();
    __syncthreads();

    float* stage = (float*)(smc + OFF_B0);
    float* sxs   = (float*)(smc + OFF_SX);
    if (tid < 128) {
        float s = 0.f;
#pragma unroll
        for (int d = 0; d < 64; ++d) { float v = stage[d * 128 + tid]; s = fmaf(v, v, s); }
        sxs[tid] = s;
    }
    // build A tile: row p, cols [xh (0..63) | unused | xl (128..191)]
    {
        int p = tid >> 1, hf = tid & 1;
        __nv_bfloat16* ar = (__nv_bfloat16*)(smc + OFF_A + p * ROWB);
#pragma unroll
        for (int k = 0; k < 32; ++k) {
            int d = hf * 32 + k;
            float xv = stage[d * 128 + p];
            __nv_bfloat16 xh = __float2bfloat16(xv);
            __nv_bfloat16 xl = __float2bfloat16(xv - __bfloat162float(xh));
            ar[d]       = xh;
            ar[128 + d] = xl;
        }
    }
    __syncthreads();            // staging dead; A + sxs ready

    // chunk0 -> B0, chunk1 -> B1 (each its own group)
#pragma unroll
    for (int q = 0; q < 7; ++q) {
        int idx = q * 256 + tid;
        if (idx < 1600) cpa16(smb + OFF_B0 + idx * 16, g_ebt[0] + idx * 16);
    }
    cpa_commit();
#pragma unroll
    for (int q = 0; q < 7; ++q) {
        int idx = q * 256 + tid;
        if (idx < 1600) cpa16(smb + OFF_B1 + idx * 16, (const char*)g_ebt[0] + 25600 + idx * 16);
    }
    cpa_commit();

    const uint32_t Abase = smb + OFF_A + (uint32_t)(mg * 32 + (lane & 15)) * ROWB
                           + (uint32_t)((lane >> 4) * 16);
    const uint32_t brow = (lane & 7) + ((lane >> 4) << 3);
    const uint32_t Boff = (uint32_t)(cg * 32 + brow) * ROWB + (uint32_t)(((lane >> 3) & 1) * 16);

    // preload xh fragments once: 4 k-groups x (2 m-tiles x 4 regs) = 32 regs
    uint32_t axh[4][8];
#pragma unroll
    for (int kk = 0; kk < 4; ++kk) {
        ldsm4(axh[kk][0], axh[kk][1], axh[kk][2], axh[kk][3], Abase + kk * 32);
        ldsm4(axh[kk][4], axh[kk][5], axh[kk][6], axh[kk][7],
              Abase + kk * 32 + 16 * ROWB);
    }

    cpa_wait1();
    __syncthreads();

    const float* sef = (const float*)(smc + OFF_SE);
    float b1v[4], b2v[4];
    int   b1i[4];
#pragma unroll
    for (int s = 0; s < 4; ++s) { b1v[s] = 3.4e38f; b2v[s] = 3.4e38f; b1i[s] = 0; }

#define UPD(s, v, ci) \
    do { float _v = (v); \
         if (_v < b1v[s]) { b2v[s] = b1v[s]; b1v[s] = _v; b1i[s] = (ci); } \
         else if (_v < b2v[s]) b2v[s] = _v; } while (0)

    for (int c = 0; c < 16; ++c) {           // 16 chunks of 64 codes
        const uint32_t Bbase = smb + ((c & 1) ? OFF_B1 : OFF_B0) + Boff;
        float acc[2][4][4];
#pragma unroll
        for (int mt = 0; mt < 2; ++mt)
#pragma unroll
            for (int nt = 0; nt < 4; ++nt)
#pragma unroll
                for (int j = 0; j < 4; ++j) acc[mt][nt][j] = 0.f;

        // unique-k mainloop: dot = xh.eh + xh.el + xl.eh per 16-k group
#pragma unroll
        for (int kk = 0; kk < 4; ++kk) {
            const uint32_t ao = (uint32_t)kk * 32;
            uint32_t beh[8], bel[8], axl[8];
            ldsm4(beh[0], beh[1], beh[2], beh[3], Bbase + ao);
            ldsm4(beh[4], beh[5], beh[6], beh[7], Bbase + ao + 16 * ROWB);
            ldsm4(bel[0], bel[1], bel[2], bel[3], Bbase + 128 + ao);
            ldsm4(bel[4], bel[5], bel[6], bel[7], Bbase + 128 + ao + 16 * ROWB);
            ldsm4(axl[0], axl[1], axl[2], axl[3], Abase + 256 + ao);
            ldsm4(axl[4], axl[5], axl[6], axl[7], Abase + 256 + ao + 16 * ROWB);
            // xh . eh
            mma16816(acc[0][0], &axh[kk][0], beh[0], beh[1]);
            mma16816(acc[0][1], &axh[kk][0], beh[2], beh[3]);
            mma16816(acc[1][0], &axh[kk][4], beh[0], beh[1]);
            mma16816(acc[1][1], &axh[kk][4], beh[2], beh[3]);
            mma16816(acc[0][2], &axh[kk][0], beh[4], beh[5]);
            mma16816(acc[0][3], &axh[kk][0], beh[6], beh[7]);
            mma16816(acc[1][2], &axh[kk][4], beh[4], beh[5]);
            mma16816(acc[1][3], &axh[kk][4], beh[6], beh[7]);
            // xh . el
            mma16816(acc[0][0], &axh[kk][0], bel[0], bel[1]);
            mma16816(acc[0][1], &axh[kk][0], bel[2], bel[3]);
            mma16816(acc[1][0], &axh[kk][4], bel[0], bel[1]);
            mma16816(acc[1][1], &axh[kk][4], bel[2], bel[3]);
            mma16816(acc[0][2], &axh[kk][0], bel[4], bel[5]);
            mma16816(acc[0][3], &axh[kk][0], bel[6], bel[7]);
            mma16816(acc[1][2], &axh[kk][4], bel[4], bel[5]);
            mma16816(acc[1][3], &axh[kk][4], bel[6], bel[7]);
            // xl . eh
            mma16816(acc[0][0], &axl[0], beh[0], beh[1]);
            mma16816(acc[0][1], &axl[0], beh[2], beh[3]);
            mma16816(acc[1][0], &axl[4], beh[0], beh[1]);
            mma16816(acc[1][1], &axl[4], beh[2], beh[3]);
            mma16816(acc[0][2], &axl[0], beh[4], beh[5]);
            mma16816(acc[0][3], &axl[0], beh[6], beh[7]);
            mma16816(acc[1][2], &axl[4], beh[4], beh[5]);
            mma16816(acc[1][3], &axl[4], beh[6], beh[7]);
        }

        const int cb0 = c * 64 + cg * 32;
#pragma unroll
        for (int mt = 0; mt < 2; ++mt) {
#pragma unroll
            for (int nt = 0; nt < 4; ++nt) {
                int cbn = cb0 + nt * 8 + 2 * lane4;
                float se0 = sef[cbn], se1 = sef[cbn + 1];
                UPD(mt * 2 + 0, fmaf(-2.f, acc[mt][nt][0], se0), cbn);
                UPD(mt * 2 + 0, fmaf(-2.f, acc[mt][nt][1], se1), cbn + 1);
                UPD(mt * 2 + 1, fmaf(-2.f, acc[mt][nt][2], se0), cbn);
                UPD(mt * 2 + 1, fmaf(-2.f, acc[mt][nt][3], se1), cbn + 1);
            }
        }

        __syncthreads();
        if (c + 2 < 16) {
            uint32_t dst = (c & 1) ? OFF_B1 : OFF_B0;
            const char* src = (const char*)g_ebt[(c + 2) >> 1] + ((c + 2) & 1) * 25600;
#pragma unroll
            for (int q = 0; q < 7; ++q) {
                int idx = q * 256 + tid;
                if (idx < 1600) cpa16(smb + dst + idx * 16, src + idx * 16);
            }
        }
        cpa_commit();
        if (c < 15) { cpa_wait1(); __syncthreads(); }
    }
#undef UPD

    // reduce across 4 column-lanes per row (tie -> lower index)
#pragma unroll
    for (int off = 1; off < 4; off <<= 1) {
#pragma unroll
        for (int s = 0; s < 4; ++s) {
            float ov1 = __shfl_xor_sync(0xffffffffu, b1v[s], off);
            float ov2 = __shfl_xor_sync(0xffffffffu, b2v[s], off);
            int   oi  = __shfl_xor_sync(0xffffffffu, b1i[s], off);
            if (ov1 < b1v[s] || (ov1 == b1v[s] && oi < b1i[s])) {
                b2v[s] = fminf(b1v[s], ov2);
                b1v[s] = ov1; b1i[s] = oi;
            } else {
                b2v[s] = fminf(b2v[s], ov1);
            }
        }
    }

    float* fb1 = (float*)(smc + OFF_FB1);
    int*   fi1 = (int*)(smc + OFF_FI1);
    float* fb2 = (float*)(smc + OFF_FB2);
    if (cg == 0 && lane4 == 0) {
#pragma unroll
        for (int s = 0; s < 4; ++s) {
            int row = mg * 32 + (s >> 1) * 16 + (s & 1) * 8 + quad;
            fb1[row] = b1v[s]; fi1[row] = b1i[s]; fb2[row] = b2v[s];
        }
    }
    __syncthreads();
    if (cg == 1 && lane4 == 0) {
#pragma unroll
        for (int s = 0; s < 4; ++s) {
            int row = mg * 32 + (s >> 1) * 16 + (s & 1) * 8 + quad;
            float ov1 = fb1[row], ov2 = fb2[row];
            int   oi  = fi1[row];
            float nb1, nb2; int ni1;
            if (ov1 < b1v[s] || (ov1 == b1v[s] && oi < b1i[s])) {
                nb1 = ov1; ni1 = oi; nb2 = fminf(b1v[s], ov2);
            } else {
                nb1 = b1v[s]; ni1 = b1i[s]; nb2 = fminf(ov1, b2v[s]);
            }
            int pt = (bb << 10) + hw0 + row;
            g_idx[pt] = ni1;
            float tau = 6e-5f * (sxs[row] + 64.f) + 1e-3f;
            if (nb2 - nb1 < tau) {
                int t = atomicAdd(scnt, 1);
                scand[t] = row;
            }
        }
    }
    __syncthreads();

    // ---- in-block exact re-solve of flagged points (bit-exact cleanup path) ----
    const int nc = *scnt;
    float* xs = (float*)(smc + OFF_B0);          // B buffers dead now
    float* rv = xs + 64;
    int*   ri = (int*)(rv + 256);
    for (int ci = 0; ci < nc; ++ci) {
        int row = scand[ci];
        if (tid < 64) xs[tid] = x[((size_t)bb << 16) + tid * HW + hw0 + row];
        __syncthreads();
        float sx = sxs[row];                     // bitwise == serial-fmaf recompute
        float dot0 = 0.f, dot1 = 0.f, dot2 = 0.f, dot3 = 0.f;
#pragma unroll
        for (int d = 0; d < 64; ++d) {
            const float* er = g_et + d * KC + tid;
            float xv = xs[d];
            dot0 = fmaf(xv, er[0],   dot0);
            dot1 = fmaf(xv, er[256], dot1);
            dot2 = fmaf(xv, er[512], dot2);
            dot3 = fmaf(xv, er[768], dot3);
        }
        float bv = 3.4e38f; int bi = 0;
        float v;
        v = __fadd_rn(__fmaf_rn(-2.f, dot0, sx), sef[tid]);
        if (v < bv) { bv = v; bi = tid; }
        v = __fadd_rn(__fmaf_rn(-2.f, dot1, sx), sef[tid + 256]);
        if (v < bv) { bv = v; bi = tid + 256; }
        v = __fadd_rn(__fmaf_rn(-2.f, dot2, sx), sef[tid + 512]);
        if (v < bv) { bv = v; bi = tid + 512; }
        v = __fadd_rn(__fmaf_rn(-2.f, dot3, sx), sef[tid + 768]);
        if (v < bv) { bv = v; bi = tid + 768; }
        rv[tid] = bv; ri[tid] = bi;
        __syncthreads();
        for (int s = 128; s; s >>= 1) {
            if (tid < s) {
                if (rv[tid + s] < rv[tid] ||
                    (rv[tid + s] == rv[tid] && ri[tid + s] < ri[tid])) {
                    rv[tid] = rv[tid + s]; ri[tid] = ri[tid + s];
                }
            }
            __syncthreads();
        }
        if (tid == 0) g_idx[(bb << 10) + hw0 + row] = ri[0];
        __syncthreads();
    }
}

// ---- gather to NCHW + hist + loss partial + fused final (last block) ----
__global__ void __launch_bounds__(256) gather_kernel(const float* __restrict__ x,
                                                     const float* __restrict__ emb,
                                                     float* __restrict__ out, int nq) {
    __shared__ int   sidx[64];
    __shared__ float qs[64 * 65];
    __shared__ float red[8];
    __shared__ int   lastblk;
    const int tid = threadIdx.x;
    const int bb  = blockIdx.x >> 4;
    const int hw0 = (blockIdx.x & 15) << 6;

    if (tid < 64) {
        int k = g_idx[(bb << 10) + hw0 + tid];
        sidx[tid] = k;
        atomicAdd(&g_hist[k], 1);
    }
    __syncthreads();
    {
        int p = tid >> 2, i = tid & 3;
        const float4* er = (const float4*)(emb + (size_t)sidx[p] * 64) + i * 4;
#pragma unroll
        for (int k = 0; k < 4; ++k) {
            float4 v = er[k];
            int d = i * 16 + k * 4;
            qs[p * 65 + d]     = v.x;
            qs[p * 65 + d + 1] = v.y;
            qs[p * 65 + d + 2] = v.z;
            qs[p * 65 + d + 3] = v.w;
        }
    }
    __syncthreads();
    const int lane = tid & 31, w = tid >> 5;
    float s = 0.f;
#pragma unroll
    for (int c8 = 0; c8 < 8; ++c8) {
        int c = w * 8 + c8;
        size_t ob = (((size_t)bb << 6) + c) * HW + hw0;
#pragma unroll
        for (int ph = 0; ph < 2; ++ph) {
            int p = ph * 32 + lane;
            float q  = qs[p * 65 + c];
            float xv = x[ob + p];
            out[ob + p] = q;
            float d = q - xv;
            s = fmaf(d, d, s);
        }
    }
#pragma unroll
    for (int off = 16; off; off >>= 1) s += __shfl_xor_sync(0xffffffffu, s, off);
    if (lane == 0) red[w] = s;
    __syncthreads();
    if (tid == 0) {
        float t = 0.f;
#pragma unroll
        for (int i = 0; i < 8; ++i) t += red[i];
        atomicAdd(&g_sumsq, (double)t);
    }

    // completion counter: last block computes loss + perplexity
    __threadfence();
    __syncthreads();
    if (tid == 0) lastblk = (atomicAdd(&g_done, 1) == (int)gridDim.x - 1);
    __syncthreads();
    if (lastblk) {
        __threadfence();
        float term = 0.f;
#pragma unroll
        for (int k = 0; k < 4; ++k) {
            float p = (float)g_hist[tid + k * 256] * (1.0f / 65536.0f);
            term += p * logf(p + 1e-10f);
        }
#pragma unroll
        for (int off = 16; off; off >>= 1) term += __shfl_xor_sync(0xffffffffu, term, off);
        if (lane == 0) red[w] = term;
        __syncthreads();
        if (tid == 0) {
            float v = 0.f;
#pragma unroll
            for (int i = 0; i < 8; ++i) v += red[i];
            float m = (float)(g_sumsq * (1.0 / (double)NELEM));
            out[nq]     = 1.25f * m;
            out[nq + 1] = expf(-v);
        }
    }
}

extern "C" void kernel_launch(void* const* d_in, const int* in_sizes, int n_in,
                              void* d_out, int out_size) {
    const float* x   = (const float*)d_in[0];
    const float* emb = (const float*)d_in[1];
    if (n_in >= 2 && in_sizes[0] == KC * 64 && in_sizes[1] == NELEM) {
        const float* tmp = x; x = emb; emb = tmp;
    }
    float* out = (float*)d_out;
    int nq = out_size - 2;

    cudaFuncSetAttribute(vq_kernel, cudaFuncAttributeMaxDynamicSharedMemorySize, SMEM_TOTAL);
    cudaFuncSetAttribute(prep_kernel, cudaFuncAttributeMaxDynamicSharedMemorySize, 84480);

    prep_kernel<<<8, 256, 84480>>>(emb);
    vq_kernel<<<512, 256, SMEM_TOTAL>>>(x);
    gather_kernel<<<NPTS / 64, 256>>>(x, emb, out, nq);
}

// round 15
// speedup vs baseline: 1.1466x; 1.0220x over previous
#include <cuda_runtime.h>
#include <cuda_bf16.h>
#include <math.h>
#include <stdint.h>

#define HW    1024
#define NPTS  65536
#define KC    1024
#define NELEM 4194304
#define ROWB  272          // tile row bytes: 128 bf16 (256B) + 16B pad (odd granule pitch)

__device__ unsigned char g_ebt[8][128 * ROWB];  // bf16 [eh|el] tiles per 128-code chunk
__device__ float  g_et[64 * KC];                // transposed emb [d][c] for exact re-solve
__device__ float  g_se[KC];
__device__ int    g_idx[NPTS];
__device__ int    g_hist[KC];
__device__ int    g_done;
__device__ double g_sumsq;

// ---- vq smem byte offsets ----
#define OFF_A   0           // 128 x 272B = 34816
#define OFF_B0  34816       // 64 x 272B = 17408 ; x staging [64][128] f32 spans B0..B0+32768
#define OFF_B1  52224       // 17408
#define OFF_SE  69632       // 4096
#define OFF_SX  73728       // 512
#define OFF_FB1 74240
#define OFF_FI1 74752
#define OFF_FB2 75264
#define OFF_CND 75776       // 128 ints candidate rows
#define OFF_CNT 76288       // counter
#define SMEM_TOTAL 76320    // x2 CTAs = 153KB <= 228KB/SM

__device__ __forceinline__ uint32_t smem_u32(const void* p) {
    uint32_t a;
    asm("{ .reg .u64 t; cvta.to.shared.u64 t, %1; cvt.u32.u64 %0, t; }" : "=r"(a) : "l"(p));
    return a;
}
__device__ __forceinline__ void cpa16(uint32_t dst, const void* src) {
    asm volatile("cp.async.cg.shared.global [%0], [%1], 16;" :: "r"(dst), "l"(src));
}
__device__ __forceinline__ void cpa_commit() { asm volatile("cp.async.commit_group;"); }
__device__ __forceinline__ void cpa_wait0()  { asm volatile("cp.async.wait_group 0;"); }
__device__ __forceinline__ void cpa_wait1()  { asm volatile("cp.async.wait_group 1;"); }

__device__ __forceinline__ void ldsm4(uint32_t& r0, uint32_t& r1, uint32_t& r2, uint32_t& r3,
                                      uint32_t addr) {
    asm volatile("ldmatrix.sync.aligned.m8n8.x4.shared.b16 {%0,%1,%2,%3}, [%4];"
                 : "=r"(r0), "=r"(r1), "=r"(r2), "=r"(r3) : "r"(addr));
}
__device__ __forceinline__ void mma16816(float* d, const uint32_t* a, uint32_t b0, uint32_t b1) {
    asm volatile("mma.sync.aligned.m16n8k16.row.col.f32.bf16.bf16.f32 "
                 "{%0,%1,%2,%3}, {%4,%5,%6,%7}, {%8,%9}, {%0,%1,%2,%3};"
                 : "+f"(d[0]), "+f"(d[1]), "+f"(d[2]), "+f"(d[3])
                 : "r"(a[0]), "r"(a[1]), "r"(a[2]), "r"(a[3]), "r"(b0), "r"(b1));
}

// ---- prep (32 blocks, one per 32-code quarter chunk): bf16 tile + g_et + se + zeroing ----
__global__ void __launch_bounds__(256) prep_kernel(const float* __restrict__ emb) {
    __shared__ float stg[32 * 65];            // 8320B, pitch 65
    __shared__ __nv_bfloat16 tile[32 * 136];  // 32 rows x 272B = 8704B
    const int tid = threadIdx.x;
    const int chunk = blockIdx.x >> 2;
    const int part = blockIdx.x & 3;
    const int c0 = chunk * 128 + part * 32;   // global code base (32 codes)

    // load 32 emb rows (2048 floats) into padded staging
#pragma unroll
    for (int q = 0; q < 2; ++q) {
        int fidx = q * 256 + tid;             // float4 id 0..511
        int code = fidx >> 4, f4 = fidx & 15;
        float4 v = ((const float4*)(emb + (size_t)c0 * 64))[fidx];
        float* d = stg + code * 65 + f4 * 4;
        d[0] = v.x; d[1] = v.y; d[2] = v.z; d[3] = v.w;
    }

    if (tid < 32) {
        int code = c0 + tid;
        g_hist[code] = 0;
        const float4* r4 = (const float4*)(emb + (size_t)code * 64);
        float s = 0.f;
#pragma unroll
        for (int i = 0; i < 16; ++i) {
            float4 v = r4[i];
            s += v.x * v.x + v.y * v.y + v.z * v.z + v.w * v.w;
        }
        g_se[code] = s;
    }
    if (blockIdx.x == 0 && tid == 32) { g_sumsq = 0.0; g_done = 0; }
    __syncthreads();

    // build bf16 tile rows: [eh (0..63) | el (64..127)]
    {
        int code = tid >> 3, seg = tid & 7;
        __nv_bfloat16* row = tile + code * 136;
        const float* sr = stg + code * 65;
#pragma unroll
        for (int k = 0; k < 8; ++k) {
            int d = seg * 8 + k;
            float ev = sr[d];
            __nv_bfloat16 eh = __float2bfloat16(ev);
            __nv_bfloat16 el = __float2bfloat16(ev - __bfloat162float(eh));
            row[d]      = eh;
            row[64 + d] = el;
        }
    }
    // transposed et (32 codes x 64 d = 2048 values)
#pragma unroll
    for (int i = 0; i < 8; ++i) {
        int idx = i * 256 + tid;
        int d = idx >> 5, cc = idx & 31;
        g_et[d * KC + c0 + cc] = stg[cc * 65 + d];
    }
    __syncthreads();
    // coalesced tile copyout: 32 x 272B = 544 float4
#pragma unroll
    for (int q = 0; q < 3; ++q) {
        int idx = q * 256 + tid;
        if (idx < 544)
            ((float4*)(g_ebt[chunk] + part * 32 * ROWB))[idx] = ((const float4*)tile)[idx];
    }
}

// ---- mma.sync vq: 128 pts x 1024 codes per block, unique-k mainloop,
//      xh fragments register-resident; in-block exact re-solve ----
__global__ void __launch_bounds__(256, 2) vq_kernel(const float* __restrict__ x) {
    extern __shared__ float sm[];
    const uint32_t smb = smem_u32(sm);
    char* smc = (char*)sm;
    const int tid = threadIdx.x;
    const int w = tid >> 5, lane = tid & 31;
    const int mg = w & 3;            // rows mg*32..mg*32+31
    const int cg = w >> 2;           // codes cg*32..cg*32+31 within 64-code chunk
    const int quad = lane >> 2, lane4 = lane & 3;
    const int bb = blockIdx.x >> 3, hw0 = (blockIdx.x & 7) << 7;
    const float* xb = x + ((size_t)bb << 16) + hw0;

    int* scnt = (int*)(smc + OFF_CNT);
    int* scand = (int*)(smc + OFF_CND);
    if (tid == 0) *scnt = 0;

    // G0: x staging at OFF_B0 (spans B0+part of B1), se
#pragma unroll
    for (int q = 0; q < 8; ++q) {
        int l = (q * 256 + tid) * 4;        // float idx in [64 d][128 p]
        cpa16(smb + OFF_B0 + l * 4, xb + (l >> 7) * HW + (l & 127));
    }
    cpa16(smb + OFF_SE + tid * 16, g_se + tid * 4);
    cpa_commit();
    cpa_wait0();
    __syncthreads();

    float* stage = (float*)(smc + OFF_B0);
    float* sxs   = (float*)(smc + OFF_SX);
    if (tid < 128) {
        float s = 0.f;
#pragma unroll
        for (int d = 0; d < 64; ++d) { float v = stage[d * 128 + tid]; s = fmaf(v, v, s); }
        sxs[tid] = s;
    }
    // build A tile: row p, cols [xh (0..63) | xl (64..127)]
    {
        int p = tid >> 1, hf = tid & 1;
        __nv_bfloat16* ar = (__nv_bfloat16*)(smc + OFF_A + p * ROWB);
#pragma unroll
        for (int k = 0; k < 32; ++k) {
            int d = hf * 32 + k;
            float xv = stage[d * 128 + p];
            __nv_bfloat16 xh = __float2bfloat16(xv);
            __nv_bfloat16 xl = __float2bfloat16(xv - __bfloat162float(xh));
            ar[d]      = xh;
            ar[64 + d] = xl;
        }
    }
    __syncthreads();            // staging dead; A + sxs ready

    // chunk0 -> B0, chunk1 -> B1 (each its own group); 1088 float4 per half
#pragma unroll
    for (int q = 0; q < 5; ++q) {
        int idx = q * 256 + tid;
        if (idx < 1088) cpa16(smb + OFF_B0 + idx * 16, g_ebt[0] + idx * 16);
    }
    cpa_commit();
#pragma unroll
    for (int q = 0; q < 5; ++q) {
        int idx = q * 256 + tid;
        if (idx < 1088) cpa16(smb + OFF_B1 + idx * 16, (const char*)g_ebt[0] + 17408 + idx * 16);
    }
    cpa_commit();

    const uint32_t Abase = smb + OFF_A + (uint32_t)(mg * 32 + (lane & 15)) * ROWB
                           + (uint32_t)((lane >> 4) * 16);
    const uint32_t brow = (lane & 7) + ((lane >> 4) << 3);
    const uint32_t Boff = (uint32_t)(cg * 32 + brow) * ROWB + (uint32_t)(((lane >> 3) & 1) * 16);

    // preload xh fragments once: 4 k-groups x (2 m-tiles x 4 regs) = 32 regs
    uint32_t axh[4][8];
#pragma unroll
    for (int kk = 0; kk < 4; ++kk) {
        ldsm4(axh[kk][0], axh[kk][1], axh[kk][2], axh[kk][3], Abase + kk * 32);
        ldsm4(axh[kk][4], axh[kk][5], axh[kk][6], axh[kk][7],
              Abase + kk * 32 + 16 * ROWB);
    }

    cpa_wait1();
    __syncthreads();

    const float* sef = (const float*)(smc + OFF_SE);
    float b1v[4], b2v[4];
    int   b1i[4];
#pragma unroll
    for (int s = 0; s < 4; ++s) { b1v[s] = 3.4e38f; b2v[s] = 3.4e38f; b1i[s] = 0; }

#define UPD(s, v, ci) \
    do { float _v = (v); \
         if (_v < b1v[s]) { b2v[s] = b1v[s]; b1v[s] = _v; b1i[s] = (ci); } \
         else if (_v < b2v[s]) b2v[s] = _v; } while (0)

    for (int c = 0; c < 16; ++c) {           // 16 chunks of 64 codes
        const uint32_t Bbase = smb + ((c & 1) ? OFF_B1 : OFF_B0) + Boff;
        float acc[2][4][4];
#pragma unroll
        for (int mt = 0; mt < 2; ++mt)
#pragma unroll
            for (int nt = 0; nt < 4; ++nt)
#pragma unroll
                for (int j = 0; j < 4; ++j) acc[mt][nt][j] = 0.f;

        // unique-k mainloop: dot = xh.eh + xh.el + xl.eh per 16-k group
#pragma unroll
        for (int kk = 0; kk < 4; ++kk) {
            const uint32_t ao = (uint32_t)kk * 32;
            uint32_t beh[8], bel[8], axl[8];
            ldsm4(beh[0], beh[1], beh[2], beh[3], Bbase + ao);
            ldsm4(beh[4], beh[5], beh[6], beh[7], Bbase + ao + 16 * ROWB);
            ldsm4(bel[0], bel[1], bel[2], bel[3], Bbase + 128 + ao);
            ldsm4(bel[4], bel[5], bel[6], bel[7], Bbase + 128 + ao + 16 * ROWB);
            ldsm4(axl[0], axl[1], axl[2], axl[3], Abase + 128 + ao);
            ldsm4(axl[4], axl[5], axl[6], axl[7], Abase + 128 + ao + 16 * ROWB);
            // xh . eh
            mma16816(acc[0][0], &axh[kk][0], beh[0], beh[1]);
            mma16816(acc[0][1], &axh[kk][0], beh[2], beh[3]);
            mma16816(acc[1][0], &axh[kk][4], beh[0], beh[1]);
            mma16816(acc[1][1], &axh[kk][4], beh[2], beh[3]);
            mma16816(acc[0][2], &axh[kk][0], beh[4], beh[5]);
            mma16816(acc[0][3], &axh[kk][0], beh[6], beh[7]);
            mma16816(acc[1][2], &axh[kk][4], beh[4], beh[5]);
            mma16816(acc[1][3], &axh[kk][4], beh[6], beh[7]);
            // xh . el
            mma16816(acc[0][0], &axh[kk][0], bel[0], bel[1]);
            mma16816(acc[0][1], &axh[kk][0], bel[2], bel[3]);
            mma16816(acc[1][0], &axh[kk][4], bel[0], bel[1]);
            mma16816(acc[1][1], &axh[kk][4], bel[2], bel[3]);
            mma16816(acc[0][2], &axh[kk][0], bel[4], bel[5]);
            mma16816(acc[0][3], &axh[kk][0], bel[6], bel[7]);
            mma16816(acc[1][2], &axh[kk][4], bel[4], bel[5]);
            mma16816(acc[1][3], &axh[kk][4], bel[6], bel[7]);
            // xl . eh
            mma16816(acc[0][0], &axl[0], beh[0], beh[1]);
            mma16816(acc[0][1], &axl[0], beh[2], beh[3]);
            mma16816(acc[1][0], &axl[4], beh[0], beh[1]);
            mma16816(acc[1][1], &axl[4], beh[2], beh[3]);
            mma16816(acc[0][2], &axl[0], beh[4], beh[5]);
            mma16816(acc[0][3], &axl[0], beh[6], beh[7]);
            mma16816(acc[1][2], &axl[4], beh[4], beh[5]);
            mma16816(acc[1][3], &axl[4], beh[6], beh[7]);
        }

        const int cb0 = c * 64 + cg * 32;
#pragma unroll
        for (int mt = 0; mt < 2; ++mt) {
#pragma unroll
            for (int nt = 0; nt < 4; ++nt) {
                int cbn = cb0 + nt * 8 + 2 * lane4;
                float se0 = sef[cbn], se1 = sef[cbn + 1];
                UPD(mt * 2 + 0, fmaf(-2.f, acc[mt][nt][0], se0), cbn);
                UPD(mt * 2 + 0, fmaf(-2.f, acc[mt][nt][1], se1), cbn + 1);
                UPD(mt * 2 + 1, fmaf(-2.f, acc[mt][nt][2], se0), cbn);
                UPD(mt * 2 + 1, fmaf(-2.f, acc[mt][nt][3], se1), cbn + 1);
            }
        }

        __syncthreads();
        if (c + 2 < 16) {
            uint32_t dst = (c & 1) ? OFF_B1 : OFF_B0;
            const char* src = (const char*)g_ebt[(c + 2) >> 1] + ((c + 2) & 1) * 17408;
#pragma unroll
            for (int q = 0; q < 5; ++q) {
                int idx = q * 256 + tid;
                if (idx < 1088) cpa16(smb + dst + idx * 16, src + idx * 16);
            }
        }
        cpa_commit();
        if (c < 15) { cpa_wait1(); __syncthreads(); }
    }
#undef UPD

    // reduce across 4 column-lanes per row (tie -> lower index)
#pragma unroll
    for (int off = 1; off < 4; off <<= 1) {
#pragma unroll
        for (int s = 0; s < 4; ++s) {
            float ov1 = __shfl_xor_sync(0xffffffffu, b1v[s], off);
            float ov2 = __shfl_xor_sync(0xffffffffu, b2v[s], off);
            int   oi  = __shfl_xor_sync(0xffffffffu, b1i[s], off);
            if (ov1 < b1v[s] || (ov1 == b1v[s] && oi < b1i[s])) {
                b2v[s] = fminf(b1v[s], ov2);
                b1v[s] = ov1; b1i[s] = oi;
            } else {
                b2v[s] = fminf(b2v[s], ov1);
            }
        }
    }

    float* fb1 = (float*)(smc + OFF_FB1);
    int*   fi1 = (int*)(smc + OFF_FI1);
    float* fb2 = (float*)(smc + OFF_FB2);
    if (cg == 0 && lane4 == 0) {
#pragma unroll
        for (int s = 0; s < 4; ++s) {
            int row = mg * 32 + (s >> 1) * 16 + (s & 1) * 8 + quad;
            fb1[row] = b1v[s]; fi1[row] = b1i[s]; fb2[row] = b2v[s];
        }
    }
    __syncthreads();
    if (cg == 1 && lane4 == 0) {
#pragma unroll
        for (int s = 0; s < 4; ++s) {
            int row = mg * 32 + (s >> 1) * 16 + (s & 1) * 8 + quad;
            float ov1 = fb1[row], ov2 = fb2[row];
            int   oi  = fi1[row];
            float nb1, nb2; int ni1;
            if (ov1 < b1v[s] || (ov1 == b1v[s] && oi < b1i[s])) {
                nb1 = ov1; ni1 = oi; nb2 = fminf(b1v[s], ov2);
            } else {
                nb1 = b1v[s]; ni1 = b1i[s]; nb2 = fminf(ov1, b2v[s]);
            }
            int pt = (bb << 10) + hw0 + row;
            g_idx[pt] = ni1;
            float tau = 6e-5f * (sxs[row] + 64.f) + 1e-3f;
            if (nb2 - nb1 < tau) {
                int t = atomicAdd(scnt, 1);
                scand[t] = row;
            }
        }
    }
    __syncthreads();

    // ---- in-block exact re-solve of flagged points (bit-exact cleanup path) ----
    const int nc = *scnt;
    float* xs = (float*)(smc + OFF_B0);          // B buffers dead now
    float* rv = xs + 64;
    int*   ri = (int*)(rv + 256);
    for (int ci = 0; ci < nc; ++ci) {
        int row = scand[ci];
        if (tid < 64) xs[tid] = x[((size_t)bb << 16) + tid * HW + hw0 + row];
        __syncthreads();
        float sx = sxs[row];                     // bitwise == serial-fmaf recompute
        float dot0 = 0.f, dot1 = 0.f, dot2 = 0.f, dot3 = 0.f;
#pragma unroll
        for (int d = 0; d < 64; ++d) {
            const float* er = g_et + d * KC + tid;
            float xv = xs[d];
            dot0 = fmaf(xv, er[0],   dot0);
            dot1 = fmaf(xv, er[256], dot1);
            dot2 = fmaf(xv, er[512], dot2);
            dot3 = fmaf(xv, er[768], dot3);
        }
        float bv = 3.4e38f; int bi = 0;
        float v;
        v = __fadd_rn(__fmaf_rn(-2.f, dot0, sx), sef[tid]);
        if (v < bv) { bv = v; bi = tid; }
        v = __fadd_rn(__fmaf_rn(-2.f, dot1, sx), sef[tid + 256]);
        if (v < bv) { bv = v; bi = tid + 256; }
        v = __fadd_rn(__fmaf_rn(-2.f, dot2, sx), sef[tid + 512]);
        if (v < bv) { bv = v; bi = tid + 512; }
        v = __fadd_rn(__fmaf_rn(-2.f, dot3, sx), sef[tid + 768]);
        if (v < bv) { bv = v; bi = tid + 768; }
        rv[tid] = bv; ri[tid] = bi;
        __syncthreads();
        for (int s = 128; s; s >>= 1) {
            if (tid < s) {
                if (rv[tid + s] < rv[tid] ||
                    (rv[tid + s] == rv[tid] && ri[tid + s] < ri[tid])) {
                    rv[tid] = rv[tid + s]; ri[tid] = ri[tid + s];
                }
            }
            __syncthreads();
        }
        if (tid == 0) g_idx[(bb << 10) + hw0 + row] = ri[0];
        __syncthreads();
    }
}

// ---- gather to NCHW + hist + loss partial + fused final (last block) ----
__global__ void __launch_bounds__(256) gather_kernel(const float* __restrict__ x,
                                                     const float* __restrict__ emb,
                                                     float* __restrict__ out, int nq) {
    __shared__ int   sidx[64];
    __shared__ float qs[64 * 65];
    __shared__ float red[8];
    __shared__ int   lastblk;
    const int tid = threadIdx.x;
    const int bb  = blockIdx.x >> 4;
    const int hw0 = (blockIdx.x & 15) << 6;

    if (tid < 64) {
        int k = g_idx[(bb << 10) + hw0 + tid];
        sidx[tid] = k;
        atomicAdd(&g_hist[k], 1);
    }
    __syncthreads();
    {
        int p = tid >> 2, i = tid & 3;
        const float4* er = (const float4*)(emb + (size_t)sidx[p] * 64) + i * 4;
#pragma unroll
        for (int k = 0; k < 4; ++k) {
            float4 v = er[k];
            int d = i * 16 + k * 4;
            qs[p * 65 + d]     = v.x;
            qs[p * 65 + d + 1] = v.y;
            qs[p * 65 + d + 2] = v.z;
            qs[p * 65 + d + 3] = v.w;
        }
    }
    __syncthreads();
    const int lane = tid & 31, w = tid >> 5;
    float s = 0.f;
#pragma unroll
    for (int c8 = 0; c8 < 8; ++c8) {
        int c = w * 8 + c8;
        size_t ob = (((size_t)bb << 6) + c) * HW + hw0;
        int p = lane * 2;
        float2 xv = *(const float2*)(x + ob + p);
        float q0 = qs[p * 65 + c];
        float q1 = qs[(p + 1) * 65 + c];
        *(float2*)(out + ob + p) = make_float2(q0, q1);
        float d0 = q0 - xv.x, d1 = q1 - xv.y;
        s = fmaf(d0, d0, s);
        s = fmaf(d1, d1, s);
    }
#pragma unroll
    for (int off = 16; off; off >>= 1) s += __shfl_xor_sync(0xffffffffu, s, off);
    if (lane == 0) red[w] = s;
    __syncthreads();
    if (tid == 0) {
        float t = 0.f;
#pragma unroll
        for (int i = 0; i < 8; ++i) t += red[i];
        atomicAdd(&g_sumsq, (double)t);
    }

    // completion counter: last block computes loss + perplexity
    __threadfence();
    __syncthreads();
    if (tid == 0) lastblk = (atomicAdd(&g_done, 1) == (int)gridDim.x - 1);
    __syncthreads();
    if (lastblk) {
        __threadfence();
        float term = 0.f;
#pragma unroll
        for (int k = 0; k < 4; ++k) {
            float p = (float)g_hist[tid + k * 256] * (1.0f / 65536.0f);
            term += p * logf(p + 1e-10f);
        }
#pragma unroll
        for (int off = 16; off; off >>= 1) term += __shfl_xor_sync(0xffffffffu, term, off);
        if (lane == 0) red[w] = term;
        __syncthreads();
        if (tid == 0) {
            float v = 0.f;
#pragma unroll
            for (int i = 0; i < 8; ++i) v += red[i];
            float m = (float)(g_sumsq * (1.0 / (double)NELEM));
            out[nq]     = 1.25f * m;
            out[nq + 1] = expf(-v);
        }
    }
}

extern "C" void kernel_launch(void* const* d_in, const int* in_sizes, int n_in,
                              void* d_out, int out_size) {
    const float* x   = (const float*)d_in[0];
    const float* emb = (const float*)d_in[1];
    if (n_in >= 2 && in_sizes[0] == KC * 64 && in_sizes[1] == NELEM) {
        const float* tmp = x; x = emb; emb = tmp;
    }
    float* out = (float*)d_out;
    int nq = out_size - 2;

    cudaFuncSetAttribute(vq_kernel, cudaFuncAttributeMaxDynamicSharedMemorySize, SMEM_TOTAL);

    prep_kernel<<<32, 256>>>(emb);
    vq_kernel<<<512, 256, SMEM_TOTAL>>>(x);
    gather_kernel<<<NPTS / 64, 256>>>(x, emb, out, nq);
}

// round 16
// speedup vs baseline: 1.1624x; 1.0137x over previous
#include <cuda_runtime.h>
#include <cuda_bf16.h>
#include <math.h>
#include <stdint.h>

#define HW    1024
#define NPTS  65536
#define KC    1024
#define NELEM 4194304
#define ROWB  272          // tile row bytes: 128 bf16 (256B) + 16B pad (odd granule pitch)

__device__ unsigned char g_ebt[8][128 * ROWB];  // bf16 [eh|el] tiles per 128-code chunk
__device__ float  g_et[64 * KC];                // transposed emb [d][c] for exact re-solve
__device__ float  g_se[KC];
__device__ int    g_idx[NPTS];
__device__ int    g_hist[KC];
__device__ int    g_done;
__device__ double g_sumsq;

// ---- vq smem byte offsets (B buffers now 128 codes each) ----
#define OFF_A   0           // 128 x 272B = 34816
#define OFF_B0  34816       // 128 x 272B = 34816 ; x staging [64][128] f32 (32768B) fits
#define OFF_B1  69632       // 34816
#define OFF_SE  104448      // 4096
#define OFF_SX  108544      // 512
#define OFF_FB1 109056
#define OFF_FI1 109568
#define OFF_FB2 110080
#define OFF_CND 110592      // 128 ints candidate rows
#define OFF_CNT 111104      // counter
#define SMEM_TOTAL 111136   // x2 CTAs = 222272 <= 228KB/SM

__device__ __forceinline__ uint32_t smem_u32(const void* p) {
    uint32_t a;
    asm("{ .reg .u64 t; cvta.to.shared.u64 t, %1; cvt.u32.u64 %0, t; }" : "=r"(a) : "l"(p));
    return a;
}
__device__ __forceinline__ void cpa16(uint32_t dst, const void* src) {
    asm volatile("cp.async.cg.shared.global [%0], [%1], 16;" :: "r"(dst), "l"(src));
}
__device__ __forceinline__ void cpa_commit() { asm volatile("cp.async.commit_group;"); }
__device__ __forceinline__ void cpa_wait0()  { asm volatile("cp.async.wait_group 0;"); }
__device__ __forceinline__ void cpa_wait1()  { asm volatile("cp.async.wait_group 1;"); }

__device__ __forceinline__ void ldsm4(uint32_t& r0, uint32_t& r1, uint32_t& r2, uint32_t& r3,
                                      uint32_t addr) {
    asm volatile("ldmatrix.sync.aligned.m8n8.x4.shared.b16 {%0,%1,%2,%3}, [%4];"
                 : "=r"(r0), "=r"(r1), "=r"(r2), "=r"(r3) : "r"(addr));
}
__device__ __forceinline__ void mma16816(float* d, const uint32_t* a, uint32_t b0, uint32_t b1) {
    asm volatile("mma.sync.aligned.m16n8k16.row.col.f32.bf16.bf16.f32 "
                 "{%0,%1,%2,%3}, {%4,%5,%6,%7}, {%8,%9}, {%0,%1,%2,%3};"
                 : "+f"(d[0]), "+f"(d[1]), "+f"(d[2]), "+f"(d[3])
                 : "r"(a[0]), "r"(a[1]), "r"(a[2]), "r"(a[3]), "r"(b0), "r"(b1));
}

// ---- prep (32 blocks, one per 32-code quarter chunk): bf16 tile + g_et + se + zeroing ----
__global__ void __launch_bounds__(256) prep_kernel(const float* __restrict__ emb) {
    __shared__ float stg[32 * 65];            // 8320B, pitch 65
    __shared__ __nv_bfloat16 tile[32 * 136];  // 32 rows x 272B = 8704B
    const int tid = threadIdx.x;
    const int chunk = blockIdx.x >> 2;
    const int part = blockIdx.x & 3;
    const int c0 = chunk * 128 + part * 32;   // global code base (32 codes)

#pragma unroll
    for (int q = 0; q < 2; ++q) {
        int fidx = q * 256 + tid;             // float4 id 0..511
        int code = fidx >> 4, f4 = fidx & 15;
        float4 v = ((const float4*)(emb + (size_t)c0 * 64))[fidx];
        float* d = stg + code * 65 + f4 * 4;
        d[0] = v.x; d[1] = v.y; d[2] = v.z; d[3] = v.w;
    }

    if (tid < 32) {
        int code = c0 + tid;
        g_hist[code] = 0;
        const float4* r4 = (const float4*)(emb + (size_t)code * 64);
        float s = 0.f;
#pragma unroll
        for (int i = 0; i < 16; ++i) {
            float4 v = r4[i];
            s += v.x * v.x + v.y * v.y + v.z * v.z + v.w * v.w;
        }
        g_se[code] = s;
    }
    if (blockIdx.x == 0 && tid == 32) { g_sumsq = 0.0; g_done = 0; }
    __syncthreads();

    {
        int code = tid >> 3, seg = tid & 7;
        __nv_bfloat16* row = tile + code * 136;
        const float* sr = stg + code * 65;
#pragma unroll
        for (int k = 0; k < 8; ++k) {
            int d = seg * 8 + k;
            float ev = sr[d];
            __nv_bfloat16 eh = __float2bfloat16(ev);
            __nv_bfloat16 el = __float2bfloat16(ev - __bfloat162float(eh));
            row[d]      = eh;
            row[64 + d] = el;
        }
    }
#pragma unroll
    for (int i = 0; i < 8; ++i) {
        int idx = i * 256 + tid;
        int d = idx >> 5, cc = idx & 31;
        g_et[d * KC + c0 + cc] = stg[cc * 65 + d];
    }
    __syncthreads();
#pragma unroll
    for (int q = 0; q < 3; ++q) {
        int idx = q * 256 + tid;
        if (idx < 544)
            ((float4*)(g_ebt[chunk] + part * 32 * ROWB))[idx] = ((const float4*)tile)[idx];
    }
}

// ---- mma.sync vq: 128 pts x 1024 codes per block, 128-code double buffers (8 chunks),
//      unique-k mainloop, xh register-resident; in-block exact re-solve ----
__global__ void __launch_bounds__(256, 2) vq_kernel(const float* __restrict__ x) {
    extern __shared__ float sm[];
    const uint32_t smb = smem_u32(sm);
    char* smc = (char*)sm;
    const int tid = threadIdx.x;
    const int w = tid >> 5, lane = tid & 31;
    const int mg = w & 3;            // rows mg*32..mg*32+31
    const int cg = w >> 2;           // 32-code slice within each 64-code half
    const int quad = lane >> 2, lane4 = lane & 3;
    const int bb = blockIdx.x >> 3, hw0 = (blockIdx.x & 7) << 7;
    const float* xb = x + ((size_t)bb << 16) + hw0;

    int* scnt = (int*)(smc + OFF_CNT);
    int* scand = (int*)(smc + OFF_CND);
    if (tid == 0) *scnt = 0;

    // G0: x staging at OFF_B0, se
#pragma unroll
    for (int q = 0; q < 8; ++q) {
        int l = (q * 256 + tid) * 4;        // float idx in [64 d][128 p]
        cpa16(smb + OFF_B0 + l * 4, xb + (l >> 7) * HW + (l & 127));
    }
    cpa16(smb + OFF_SE + tid * 16, g_se + tid * 4);
    cpa_commit();
    cpa_wait0();
    __syncthreads();

    float* stage = (float*)(smc + OFF_B0);
    float* sxs   = (float*)(smc + OFF_SX);
    if (tid < 128) {
        float s = 0.f;
#pragma unroll
        for (int d = 0; d < 64; ++d) { float v = stage[d * 128 + tid]; s = fmaf(v, v, s); }
        sxs[tid] = s;
    }
    // build A tile: row p, cols [xh (0..63) | xl (64..127)]
    {
        int p = tid >> 1, hf = tid & 1;
        __nv_bfloat16* ar = (__nv_bfloat16*)(smc + OFF_A + p * ROWB);
#pragma unroll
        for (int k = 0; k < 32; ++k) {
            int d = hf * 32 + k;
            float xv = stage[d * 128 + p];
            __nv_bfloat16 xh = __float2bfloat16(xv);
            __nv_bfloat16 xl = __float2bfloat16(xv - __bfloat162float(xh));
            ar[d]      = xh;
            ar[64 + d] = xl;
        }
    }
    __syncthreads();            // staging dead; A + sxs ready

    // chunk0 -> B0, chunk1 -> B1 (128 codes each = 2176 float4)
#pragma unroll
    for (int q = 0; q < 9; ++q) {
        int idx = q * 256 + tid;
        if (idx < 2176) cpa16(smb + OFF_B0 + idx * 16, g_ebt[0] + idx * 16);
    }
    cpa_commit();
#pragma unroll
    for (int q = 0; q < 9; ++q) {
        int idx = q * 256 + tid;
        if (idx < 2176) cpa16(smb + OFF_B1 + idx * 16, g_ebt[1] + idx * 16);
    }
    cpa_commit();

    const uint32_t Abase = smb + OFF_A + (uint32_t)(mg * 32 + (lane & 15)) * ROWB
                           + (uint32_t)((lane >> 4) * 16);
    const uint32_t brow = (lane & 7) + ((lane >> 4) << 3);
    const uint32_t Boff = (uint32_t)(cg * 32 + brow) * ROWB + (uint32_t)(((lane >> 3) & 1) * 16);

    // preload xh fragments once
    uint32_t axh[4][8];
#pragma unroll
    for (int kk = 0; kk < 4; ++kk) {
        ldsm4(axh[kk][0], axh[kk][1], axh[kk][2], axh[kk][3], Abase + kk * 32);
        ldsm4(axh[kk][4], axh[kk][5], axh[kk][6], axh[kk][7],
              Abase + kk * 32 + 16 * ROWB);
    }

    cpa_wait1();
    __syncthreads();

    const float* sef = (const float*)(smc + OFF_SE);
    float b1v[4], b2v[4];
    int   b1i[4];
#pragma unroll
    for (int s = 0; s < 4; ++s) { b1v[s] = 3.4e38f; b2v[s] = 3.4e38f; b1i[s] = 0; }

#define UPD(s, v, ci) \
    do { float _v = (v); \
         if (_v < b1v[s]) { b2v[s] = b1v[s]; b1v[s] = _v; b1i[s] = (ci); } \
         else if (_v < b2v[s]) b2v[s] = _v; } while (0)

    for (int c = 0; c < 8; ++c) {            // 8 chunks of 128 codes
        const uint32_t bufb = smb + ((c & 1) ? OFF_B1 : OFF_B0);

        // two 64-code halves from the resident buffer, no barrier between
#pragma unroll
        for (int h = 0; h < 2; ++h) {
            const uint32_t Bbase = bufb + (uint32_t)(h * 64) * ROWB + Boff;
            float acc[2][4][4];
#pragma unroll
            for (int mt = 0; mt < 2; ++mt)
#pragma unroll
                for (int nt = 0; nt < 4; ++nt)
#pragma unroll
                    for (int j = 0; j < 4; ++j) acc[mt][nt][j] = 0.f;

#pragma unroll
            for (int kk = 0; kk < 4; ++kk) {
                const uint32_t ao = (uint32_t)kk * 32;
                uint32_t beh[8], bel[8], axl[8];
                ldsm4(beh[0], beh[1], beh[2], beh[3], Bbase + ao);
                ldsm4(beh[4], beh[5], beh[6], beh[7], Bbase + ao + 16 * ROWB);
                ldsm4(bel[0], bel[1], bel[2], bel[3], Bbase + 128 + ao);
                ldsm4(bel[4], bel[5], bel[6], bel[7], Bbase + 128 + ao + 16 * ROWB);
                ldsm4(axl[0], axl[1], axl[2], axl[3], Abase + 128 + ao);
                ldsm4(axl[4], axl[5], axl[6], axl[7], Abase + 128 + ao + 16 * ROWB);
                // xh . eh
                mma16816(acc[0][0], &axh[kk][0], beh[0], beh[1]);
                mma16816(acc[0][1], &axh[kk][0], beh[2], beh[3]);
                mma16816(acc[1][0], &axh[kk][4], beh[0], beh[1]);
                mma16816(acc[1][1], &axh[kk][4], beh[2], beh[3]);
                mma16816(acc[0][2], &axh[kk][0], beh[4], beh[5]);
                mma16816(acc[0][3], &axh[kk][0], beh[6], beh[7]);
                mma16816(acc[1][2], &axh[kk][4], beh[4], beh[5]);
                mma16816(acc[1][3], &axh[kk][4], beh[6], beh[7]);
                // xh . el
                mma16816(acc[0][0], &axh[kk][0], bel[0], bel[1]);
                mma16816(acc[0][1], &axh[kk][0], bel[2], bel[3]);
                mma16816(acc[1][0], &axh[kk][4], bel[0], bel[1]);
                mma16816(acc[1][1], &axh[kk][4], bel[2], bel[3]);
                mma16816(acc[0][2], &axh[kk][0], bel[4], bel[5]);
                mma16816(acc[0][3], &axh[kk][0], bel[6], bel[7]);
                mma16816(acc[1][2], &axh[kk][4], bel[4], bel[5]);
                mma16816(acc[1][3], &axh[kk][4], bel[6], bel[7]);
                // xl . eh
                mma16816(acc[0][0], &axl[0], beh[0], beh[1]);
                mma16816(acc[0][1], &axl[0], beh[2], beh[3]);
                mma16816(acc[1][0], &axl[4], beh[0], beh[1]);
                mma16816(acc[1][1], &axl[4], beh[2], beh[3]);
                mma16816(acc[0][2], &axl[0], beh[4], beh[5]);
                mma16816(acc[0][3], &axl[0], beh[6], beh[7]);
                mma16816(acc[1][2], &axl[4], beh[4], beh[5]);
                mma16816(acc[1][3], &axl[4], beh[6], beh[7]);
            }

            const int cb0 = c * 128 + h * 64 + cg * 32;
#pragma unroll
            for (int mt = 0; mt < 2; ++mt) {
#pragma unroll
                for (int nt = 0; nt < 4; ++nt) {
                    int cbn = cb0 + nt * 8 + 2 * lane4;
                    float se0 = sef[cbn], se1 = sef[cbn + 1];
                    UPD(mt * 2 + 0, fmaf(-2.f, acc[mt][nt][0], se0), cbn);
                    UPD(mt * 2 + 0, fmaf(-2.f, acc[mt][nt][1], se1), cbn + 1);
                    UPD(mt * 2 + 1, fmaf(-2.f, acc[mt][nt][2], se0), cbn);
                    UPD(mt * 2 + 1, fmaf(-2.f, acc[mt][nt][3], se1), cbn + 1);
                }
            }
        }

        __syncthreads();        // all warps done reading buffer c
        if (c + 2 < 8) {
            uint32_t dst = (c & 1) ? OFF_B1 : OFF_B0;
            const unsigned char* src = g_ebt[c + 2];
#pragma unroll
            for (int q = 0; q < 9; ++q) {
                int idx = q * 256 + tid;
                if (idx < 2176) cpa16(smb + dst + idx * 16, src + idx * 16);
            }
        }
        cpa_commit();
        if (c < 7) { cpa_wait1(); __syncthreads(); }
    }
#undef UPD

    // reduce across 4 column-lanes per row (tie -> lower index)
#pragma unroll
    for (int off = 1; off < 4; off <<= 1) {
#pragma unroll
        for (int s = 0; s < 4; ++s) {
            float ov1 = __shfl_xor_sync(0xffffffffu, b1v[s], off);
            float ov2 = __shfl_xor_sync(0xffffffffu, b2v[s], off);
            int   oi  = __shfl_xor_sync(0xffffffffu, b1i[s], off);
            if (ov1 < b1v[s] || (ov1 == b1v[s] && oi < b1i[s])) {
                b2v[s] = fminf(b1v[s], ov2);
                b1v[s] = ov1; b1i[s] = oi;
            } else {
                b2v[s] = fminf(b2v[s], ov1);
            }
        }
    }

    float* fb1 = (float*)(smc + OFF_FB1);
    int*   fi1 = (int*)(smc + OFF_FI1);
    float* fb2 = (float*)(smc + OFF_FB2);
    if (cg == 0 && lane4 == 0) {
#pragma unroll
        for (int s = 0; s < 4; ++s) {
            int row = mg * 32 + (s >> 1) * 16 + (s & 1) * 8 + quad;
            fb1[row] = b1v[s]; fi1[row] = b1i[s]; fb2[row] = b2v[s];
        }
    }
    __syncthreads();
    if (cg == 1 && lane4 == 0) {
#pragma unroll
        for (int s = 0; s < 4; ++s) {
            int row = mg * 32 + (s >> 1) * 16 + (s & 1) * 8 + quad;
            float ov1 = fb1[row], ov2 = fb2[row];
            int   oi  = fi1[row];
            float nb1, nb2; int ni1;
            if (ov1 < b1v[s] || (ov1 == b1v[s] && oi < b1i[s])) {
                nb1 = ov1; ni1 = oi; nb2 = fminf(b1v[s], ov2);
            } else {
                nb1 = b1v[s]; ni1 = b1i[s]; nb2 = fminf(ov1, b2v[s]);
            }
            int pt = (bb << 10) + hw0 + row;
            g_idx[pt] = ni1;
            float tau = 6e-5f * (sxs[row] + 64.f) + 1e-3f;
            if (nb2 - nb1 < tau) {
                int t = atomicAdd(scnt, 1);
                scand[t] = row;
            }
        }
    }
    __syncthreads();

    // ---- in-block exact re-solve of flagged points (bit-exact cleanup path) ----
    const int nc = *scnt;
    float* xs = (float*)(smc + OFF_B0);          // B buffers dead now
    float* rv = xs + 64;
    int*   ri = (int*)(rv + 256);
    for (int ci = 0; ci < nc; ++ci) {
        int row = scand[ci];
        if (tid < 64) xs[tid] = x[((size_t)bb << 16) + tid * HW + hw0 + row];
        __syncthreads();
        float sx = sxs[row];                     // bitwise == serial-fmaf recompute
        float dot0 = 0.f, dot1 = 0.f, dot2 = 0.f, dot3 = 0.f;
#pragma unroll
        for (int d = 0; d < 64; ++d) {
            const float* er = g_et + d * KC + tid;
            float xv = xs[d];
            dot0 = fmaf(xv, er[0],   dot0);
            dot1 = fmaf(xv, er[256], dot1);
            dot2 = fmaf(xv, er[512], dot2);
            dot3 = fmaf(xv, er[768], dot3);
        }
        float bv = 3.4e38f; int bi = 0;
        float v;
        v = __fadd_rn(__fmaf_rn(-2.f, dot0, sx), sef[tid]);
        if (v < bv) { bv = v; bi = tid; }
        v = __fadd_rn(__fmaf_rn(-2.f, dot1, sx), sef[tid + 256]);
        if (v < bv) { bv = v; bi = tid + 256; }
        v = __fadd_rn(__fmaf_rn(-2.f, dot2, sx), sef[tid + 512]);
        if (v < bv) { bv = v; bi = tid + 512; }
        v = __fadd_rn(__fmaf_rn(-2.f, dot3, sx), sef[tid + 768]);
        if (v < bv) { bv = v; bi = tid + 768; }
        rv[tid] = bv; ri[tid] = bi;
        __syncthreads();
        for (int s = 128; s; s >>= 1) {
            if (tid < s) {
                if (rv[tid + s] < rv[tid] ||
                    (rv[tid + s] == rv[tid] && ri[tid + s] < ri[tid])) {
                    rv[tid] = rv[tid + s]; ri[tid] = ri[tid + s];
                }
            }
            __syncthreads();
        }
        if (tid == 0) g_idx[(bb << 10) + hw0 + row] = ri[0];
        __syncthreads();
    }
}

// ---- gather to NCHW + hist + loss partial + fused final (last block) ----
__global__ void __launch_bounds__(256) gather_kernel(const float* __restrict__ x,
                                                     const float* __restrict__ emb,
                                                     float* __restrict__ out, int nq) {
    __shared__ int   sidx[64];
    __shared__ float qs[64 * 65];
    __shared__ float red[8];
    __shared__ int   lastblk;
    const int tid = threadIdx.x;
    const int bb  = blockIdx.x >> 4;
    const int hw0 = (blockIdx.x & 15) << 6;

    if (tid < 64) {
        int k = g_idx[(bb << 10) + hw0 + tid];
        sidx[tid] = k;
        atomicAdd(&g_hist[k], 1);
    }
    __syncthreads();
    {
        int p = tid >> 2, i = tid & 3;
        const float4* er = (const float4*)(emb + (size_t)sidx[p] * 64) + i * 4;
#pragma unroll
        for (int k = 0; k < 4; ++k) {
            float4 v = er[k];
            int d = i * 16 + k * 4;
            qs[p * 65 + d]     = v.x;
            qs[p * 65 + d + 1] = v.y;
            qs[p * 65 + d + 2] = v.z;
            qs[p * 65 + d + 3] = v.w;
        }
    }
    __syncthreads();
    const int lane = tid & 31, w = tid >> 5;
    float s = 0.f;
#pragma unroll
    for (int c8 = 0; c8 < 8; ++c8) {
        int c = w * 8 + c8;
        size_t ob = (((size_t)bb << 6) + c) * HW + hw0;
        int p = lane * 2;
        float2 xv = *(const float2*)(x + ob + p);
        float q0 = qs[p * 65 + c];
        float q1 = qs[(p + 1) * 65 + c];
        *(float2*)(out + ob + p) = make_float2(q0, q1);
        float d0 = q0 - xv.x, d1 = q1 - xv.y;
        s = fmaf(d0, d0, s);
        s = fmaf(d1, d1, s);
    }
#pragma unroll
    for (int off = 16; off; off >>= 1) s += __shfl_xor_sync(0xffffffffu, s, off);
    if (lane == 0) red[w] = s;
    __syncthreads();
    if (tid == 0) {
        float t = 0.f;
#pragma unroll
        for (int i = 0; i < 8; ++i) t += red[i];
        atomicAdd(&g_sumsq, (double)t);
    }

    __threadfence();
    __syncthreads();
    if (tid == 0) lastblk = (atomicAdd(&g_done, 1) == (int)gridDim.x - 1);
    __syncthreads();
    if (lastblk) {
        __threadfence();
        float term = 0.f;
#pragma unroll
        for (int k = 0; k < 4; ++k) {
            float p = (float)g_hist[tid + k * 256] * (1.0f / 65536.0f);
            term += p * logf(p + 1e-10f);
        }
#pragma unroll
        for (int off = 16; off; off >>= 1) term += __shfl_xor_sync(0xffffffffu, term, off);
        if (lane == 0) red[w] = term;
        __syncthreads();
        if (tid == 0) {
            float v = 0.f;
#pragma unroll
            for (int i = 0; i < 8; ++i) v += red[i];
            float m = (float)(g_sumsq * (1.0 / (double)NELEM));
            out[nq]     = 1.25f * m;
            out[nq + 1] = expf(-v);
        }
    }
}

extern "C" void kernel_launch(void* const* d_in, const int* in_sizes, int n_in,
                              void* d_out, int out_size) {
    const float* x   = (const float*)d_in[0];
    const float* emb = (const float*)d_in[1];
    if (n_in >= 2 && in_sizes[0] == KC * 64 && in_sizes[1] == NELEM) {
        const float* tmp = x; x = emb; emb = tmp;
    }
    float* out = (float*)d_out;
    int nq = out_size - 2;

    cudaFuncSetAttribute(vq_kernel, cudaFuncAttributeMaxDynamicSharedMemorySize, SMEM_TOTAL);

    prep_kernel<<<32, 256>>>(emb);
    vq_kernel<<<512, 256, SMEM_TOTAL>>>(x);
    gather_kernel<<<NPTS / 64, 256>>>(x, emb, out, nq);
}